// round 12
// baseline (speedup 1.0000x reference)
#include <cuda_runtime.h>
#include <cuda_bf16.h>
#include <math.h>
#include <cstdint>

#define BSZ 4
#define SEQ 2048
#define DIM 2048
#define NHEADS 16
#define NKV 4
#define HD 128
#define KVD 512
#define NTOK (BSZ*SEQ)
#define GK 2048
#define QKVD 3072
#define QFAC (0.088388347648318447f * 1.4426950408889634f)

#if !defined(__CUDA_ARCH__) || defined(__CUDA_ARCH_FEAT_SM103_ALL) || defined(__CUDA_ARCH_FEAT_SM100_ALL)
#define HAS_TCGEN05 1
#else
#define HAS_TCGEN05 0
#endif

__device__ float g_qkv[(size_t)NTOK * QKVD];
__device__ __nv_bfloat16 g_xhi[(size_t)NTOK * DIM];
__device__ __nv_bfloat16 g_xlo[(size_t)NTOK * DIM];
__device__ __nv_bfloat16 g_yhi[(size_t)NTOK * DIM];
__device__ __nv_bfloat16 g_ylo[(size_t)NTOK * DIM];
__device__ __nv_bfloat16 g_qhi[(size_t)NTOK * DIM];
__device__ __nv_bfloat16 g_qlo[(size_t)NTOK * DIM];
__device__ __nv_bfloat16 g_khi[(size_t)NTOK * KVD];
__device__ __nv_bfloat16 g_klo[(size_t)NTOK * KVD];
__device__ __nv_bfloat16 g_vthi[(size_t)NTOK * KVD];   // [b][kvh][d][SEQ]
__device__ __nv_bfloat16 g_vtlo[(size_t)NTOK * KVD];
__device__ __nv_bfloat16 g_wqkvhi[(size_t)QKVD * GK];
__device__ __nv_bfloat16 g_wqkvlo[(size_t)QKVD * GK];
__device__ __nv_bfloat16 g_wohi[(size_t)DIM * DIM];
__device__ __nv_bfloat16 g_wolo[(size_t)DIM * DIM];
__device__ float g_cos[SEQ * 64];
__device__ float g_sin[SEQ * 64];

__device__ __forceinline__ uint32_t smem_u32(const void* p) {
    uint32_t a;
    asm("{ .reg .u64 t; cvta.to.shared.u64 t, %1; cvt.u32.u64 %0, t; }" : "=r"(a) : "l"(p));
    return a;
}
#define SWZ(o) ((o) ^ (((o) >> 3) & 0x70))
#define CP_ASYNC16(dst, src) \
    asm volatile("cp.async.cg.shared.global [%0], [%1], 16;" :: "r"(dst), "l"(src) : "memory")
#define CP_COMMIT() asm volatile("cp.async.commit_group;" ::: "memory")
#define CP_WAIT(n)  asm volatile("cp.async.wait_group %0;" :: "n"(n) : "memory")
#define MBAR_INIT(a, c) \
    asm volatile("mbarrier.init.shared.b64 [%0], %1;" :: "r"(a), "r"(c) : "memory")
#define MBAR_WAIT(a, ph) do { \
    uint32_t _m = (a), _p = (ph), _d; \
    asm volatile("{\n .reg .pred p;\n mbarrier.try_wait.parity.acquire.cta.shared::cta.b64 p, [%1], %2;\n selp.b32 %0,1,0,p;\n}" \
        : "=r"(_d) : "r"(_m), "r"(_p) : "memory"); \
    if (!_d) { \
        asm volatile("{\n .reg .pred P1;\nWL%=:\n mbarrier.try_wait.parity.acquire.cta.shared::cta.b64 P1, [%0], %1, 0x989680;\n @P1 bra.uni WD%=;\n bra.uni WL%=;\nWD%=:\n}" \
            :: "r"(_m), "r"(_p) : "memory"); \
    } } while (0)
#define MBAR_ARRIVE_LEADER(a) \
    asm volatile("{\n .reg .b32 la;\n and.b32 la, %0, 0xFEFFFFFF;\n" \
        " mbarrier.arrive.shared::cluster.b64 _, [la];\n}" :: "r"(a) : "memory")
#define CLUSTER_SYNC() do { \
    asm volatile("barrier.cluster.arrive.aligned;" ::: "memory"); \
    asm volatile("barrier.cluster.wait.aligned;" ::: "memory"); } while (0)
#define FENCE_PROXY_ASYNC() asm volatile("fence.proxy.async.shared::cta;" ::: "memory")

__device__ __forceinline__ float fast_ex2(float x) {
    float r; asm("ex2.approx.ftz.f32 %0, %1;" : "=f"(r) : "f"(x)); return r;
}
__device__ __forceinline__ uint32_t pack_bf16x2(float lo, float hi) {
    uint32_t r; asm("cvt.rn.bf16x2.f32 %0, %1, %2;" : "=r"(r) : "f"(hi), "f"(lo)); return r;
}

#define T2M 256
#define T2N 256
#define NST2 3
#define NCHUNK (GK / 64)
#define ST2_BYTES (4 * 16384)
#define GEMM2_SMEM (2048 + NST2 * ST2_BYTES)
#define GEMM2_IDESC ((1u<<4) | (1u<<7) | (1u<<10) | ((T2N/8)<<17) | ((T2M/16)<<24))

#define FL_STAGEB 65536
#define FL_SMEM (2048 + 3 * FL_STAGEB)
#define TQHI 0
#define TQLO 64
#define TO   128
#define TS(st)  (256 + (st) * 64)
#define TPH(st) (384 + (st) * 64)
#define TPL(st) (384 + (st) * 64 + 32)
#define IDQ  ((1u<<4)|(1u<<7)|(1u<<10)|((64/8)<<17)|((128/16)<<24))
#define IDPV ((1u<<4)|(1u<<7)|(1u<<10)|((128/8)<<17)|((128/16)<<24))
#define B2C  17.0f

#if HAS_TCGEN05

__device__ __forceinline__ uint32_t elect1() {
    uint32_t p;
    asm volatile("{.reg .pred P; elect.sync _|P, 0xFFFFFFFF; selp.b32 %0,1,0,P;}" : "=r"(p));
    return p;
}
#define TCGEN05_ALLOC(a, n) \
    asm volatile("tcgen05.alloc.cta_group::1.sync.aligned.shared::cta.b32 [%0], %1;" :: "r"(a), "r"(n) : "memory")
#define TCGEN05_RELINQ() asm volatile("tcgen05.relinquish_alloc_permit.cta_group::1.sync.aligned;")
#define TCGEN05_DEALLOC(t, n) \
    asm volatile("tcgen05.dealloc.cta_group::1.sync.aligned.b32 %0, %1;" :: "r"(t), "r"(n))
#define TCGEN05_ALLOC_CG2(a, n) \
    asm volatile("tcgen05.alloc.cta_group::2.sync.aligned.shared::cta.b32 [%0], %1;" :: "r"(a), "r"(n) : "memory")
#define TCGEN05_RELINQ_CG2() asm volatile("tcgen05.relinquish_alloc_permit.cta_group::2.sync.aligned;")
#define TCGEN05_DEALLOC_CG2(t, n) \
    asm volatile("tcgen05.dealloc.cta_group::2.sync.aligned.b32 %0, %1;" :: "r"(t), "r"(n))
#define TCGEN05_COMMIT(m) \
    asm volatile("tcgen05.commit.cta_group::1.mbarrier::arrive::one.shared::cluster.b64 [%0];" :: "r"(m) : "memory")
#define TCGEN05_COMMIT_MC_CG2(m, mask) \
    asm volatile("tcgen05.commit.cta_group::2.mbarrier::arrive::one.shared::cluster.multicast::cluster.b64 [%0], %1;" \
        :: "r"(m), "h"((uint16_t)(mask)) : "memory")
#define TCGEN05_FENCE_BEFORE() asm volatile("tcgen05.fence::before_thread_sync;" ::: "memory")
#define TCGEN05_FENCE_AFTER()  asm volatile("tcgen05.fence::after_thread_sync;" ::: "memory")
#define TCGEN05_WAIT_LD() asm volatile("tcgen05.wait::ld.sync.aligned;" ::: "memory")
#define TCGEN05_WAIT_ST() asm volatile("tcgen05.wait::st.sync.aligned;" ::: "memory")

#define LDTM_X32(r, a) \
    asm volatile("tcgen05.ld.sync.aligned.32x32b.x32.b32 " \
        "{%0,%1,%2,%3,%4,%5,%6,%7,%8,%9,%10,%11,%12,%13,%14,%15," \
        "%16,%17,%18,%19,%20,%21,%22,%23,%24,%25,%26,%27,%28,%29,%30,%31}, [%32];" \
        : "=r"((r)[0]),"=r"((r)[1]),"=r"((r)[2]),"=r"((r)[3]),"=r"((r)[4]),"=r"((r)[5]),"=r"((r)[6]),"=r"((r)[7]), \
          "=r"((r)[8]),"=r"((r)[9]),"=r"((r)[10]),"=r"((r)[11]),"=r"((r)[12]),"=r"((r)[13]),"=r"((r)[14]),"=r"((r)[15]), \
          "=r"((r)[16]),"=r"((r)[17]),"=r"((r)[18]),"=r"((r)[19]),"=r"((r)[20]),"=r"((r)[21]),"=r"((r)[22]),"=r"((r)[23]), \
          "=r"((r)[24]),"=r"((r)[25]),"=r"((r)[26]),"=r"((r)[27]),"=r"((r)[28]),"=r"((r)[29]),"=r"((r)[30]),"=r"((r)[31]) \
        : "r"(a))
#define STTM_X32(a, r) \
    asm volatile("tcgen05.st.sync.aligned.32x32b.x32.b32 [%0], " \
        "{%1,%2,%3,%4,%5,%6,%7,%8,%9,%10,%11,%12,%13,%14,%15,%16," \
        "%17,%18,%19,%20,%21,%22,%23,%24,%25,%26,%27,%28,%29,%30,%31,%32};" \
        :: "r"(a), \
           "r"((r)[0]),"r"((r)[1]),"r"((r)[2]),"r"((r)[3]),"r"((r)[4]),"r"((r)[5]),"r"((r)[6]),"r"((r)[7]), \
           "r"((r)[8]),"r"((r)[9]),"r"((r)[10]),"r"((r)[11]),"r"((r)[12]),"r"((r)[13]),"r"((r)[14]),"r"((r)[15]), \
           "r"((r)[16]),"r"((r)[17]),"r"((r)[18]),"r"((r)[19]),"r"((r)[20]),"r"((r)[21]),"r"((r)[22]),"r"((r)[23]), \
           "r"((r)[24]),"r"((r)[25]),"r"((r)[26]),"r"((r)[27]),"r"((r)[28]),"r"((r)[29]),"r"((r)[30]),"r"((r)[31]) \
        : "memory")

__device__ __forceinline__ uint64_t mk_desc(uint32_t addr) {
    const uint64_t base = (uint64_t(2) << 61) | (uint64_t(1) << 46) |
                          (uint64_t(64) << 32) | (uint64_t(1) << 16);
    return base | ((addr >> 4) & 0x3FFF);
}
__device__ __forceinline__ void mma_ss_cg2(uint32_t d, uint64_t ad, uint64_t bd,
                                           uint32_t idesc, uint32_t en) {
    asm volatile("{\n .reg .pred p;\n setp.ne.u32 p, %5, 0;\n"
        " tcgen05.mma.cta_group::2.kind::f16 [%0], %1, %2, %3, "
        "{%4,%4,%4,%4,%4,%4,%4,%4}, p;\n}"
        :: "r"(d), "l"(ad), "l"(bd), "r"(idesc), "r"(0u), "r"(en) : "memory");
}
__device__ __forceinline__ void mma_ts(uint32_t d, uint32_t a, uint64_t bd,
                                       uint32_t idesc, uint32_t en) {
    asm volatile("{\n .reg .pred p;\n setp.ne.u32 p, %4, 0;\n"
        " tcgen05.mma.cta_group::1.kind::f16 [%0], [%1], %2, %3, {%5,%5,%5,%5}, p;\n}"
        :: "r"(d), "r"(a), "l"(bd), "r"(idesc), "r"(en), "r"(0u) : "memory");
}

// ---------------- cg2 bf16x3 GEMM, warp-specialized loader/issuer --------
// Fix vs R11: __syncthreads() before the final war-wait so every thread is
// past the chunk-31 full-arrival (slot phase bit guaranteed 0 there), making
// the final parity-0 wait block until the true last commit.
__global__ __launch_bounds__(128, 1) __cluster_dims__(2, 1, 1)
void gemm2_kernel(
    float* __restrict__ C,
    const __nv_bfloat16* __restrict__ Ahi, const __nv_bfloat16* __restrict__ Alo,
    const __nv_bfloat16* __restrict__ Bhi, const __nv_bfloat16* __restrict__ Blo,
    int N)
{
    extern __shared__ char sm[];
    const uint32_t sbase = smem_u32(sm);
    const uint32_t war0  = sbase + 8;
    const uint32_t full0 = sbase + 32;
    const uint32_t tile0 = (sbase + 64 + 1023) & ~1023u;
    const int tid = threadIdx.x, wid = tid >> 5, lid = tid & 31;
    const int rank = blockIdx.x & 1;
    const int bn = (blockIdx.x >> 1) * T2N;
    const int bm = blockIdx.y * T2M;

    if (tid == 0) {
        #pragma unroll
        for (int s = 0; s < NST2; s++) {
            MBAR_INIT(war0 + s * 8, 1);
            MBAR_INIT(full0 + s * 8, 192);   // 96 loaders x 2 CTAs
        }
    }
    if (wid == 0) { TCGEN05_ALLOC_CG2(sbase, 256); TCGEN05_RELINQ_CG2(); }
    __syncthreads();
    uint32_t tmem;
    asm volatile("ld.shared.b32 %0, [%1];" : "=r"(tmem) : "r"(sbase));
    CLUSTER_SYNC();   // all mbars initialized before cross-CTA traffic

    if (wid >= 1) {
        // ---- loaders: 96 threads, 11 predicated granule rounds / chunk ----
        const int lt = tid - 32;   // 0..95
        const char* Abase = (const char*)Ahi + (size_t)(bm + rank * 128) * (GK * 2);
        const char* Albase = (const char*)Alo + (size_t)(bm + rank * 128) * (GK * 2);
        const char* Bbase = (const char*)Bhi + (size_t)(bn + rank * 128) * (GK * 2);
        const char* Blbase = (const char*)Blo + (size_t)(bn + rank * 128) * (GK * 2);
        auto load_chunk = [&](int c) {
            uint32_t st = tile0 + (c % 3) * ST2_BYTES;
            #pragma unroll
            for (int i = 0; i < 11; i++) {
                int g = lt + i * 96;
                if (g < 1024) {
                    int row = g >> 3, seg = g & 7;
                    uint32_t so = SWZ((uint32_t)(row * 128 + seg * 16));
                    size_t go = (size_t)row * (GK * 2) + c * 128 + seg * 16;
                    CP_ASYNC16(st + so,         Abase + go);
                    CP_ASYNC16(st + 16384 + so, Albase + go);
                    CP_ASYNC16(st + 32768 + so, Bbase + go);
                    CP_ASYNC16(st + 49152 + so, Blbase + go);
                }
            }
        };
        load_chunk(0); CP_COMMIT();
        load_chunk(1); CP_COMMIT();
        for (int c = 0; c < NCHUNK; c++) {
            const int cl = c + 2;
            if (cl < NCHUNK) {
                if (cl >= NST2) MBAR_WAIT(war0 + (cl % 3) * 8, ((cl / 3) + 1) & 1);
                load_chunk(cl);
            }
            CP_COMMIT();
            CP_WAIT(2);               // chunk c resident (this thread)
            FENCE_PROXY_ASYNC();
            MBAR_ARRIVE_LEADER(full0 + (c % 3) * 8);
        }
    } else if (rank == 0 && elect1()) {
        // ---- issuer: MMA at tensor-pipe rate, gated only on full(c) ----
        for (int c = 0; c < NCHUNK; c++) {
            MBAR_WAIT(full0 + (c % 3) * 8, (c / 3) & 1);
            uint32_t st = tile0 + (c % 3) * ST2_BYTES;
            uint64_t adh = mk_desc(st),         adl = mk_desc(st + 16384);
            uint64_t bdh = mk_desc(st + 32768), bdl = mk_desc(st + 49152);
            #pragma unroll
            for (int s = 0; s < 4; s++)
                mma_ss_cg2(tmem, adh + s * 2, bdh + s * 2, GEMM2_IDESC,
                           (uint32_t)((c | s) != 0));
            #pragma unroll
            for (int s = 0; s < 4; s++)
                mma_ss_cg2(tmem, adl + s * 2, bdh + s * 2, GEMM2_IDESC, 1u);
            #pragma unroll
            for (int s = 0; s < 4; s++)
                mma_ss_cg2(tmem, adh + s * 2, bdl + s * 2, GEMM2_IDESC, 1u);
            TCGEN05_COMMIT_MC_CG2(war0 + (c % 3) * 8, 0x3);
        }
    }

    // ---- epilogue ----
    // Sync first: every thread is then past the loaders' chunk-31 full
    // arrival, so the last war slot has exactly 10 flips (bit 0) and the
    // parity-0 wait below blocks until the true 11th (final) commit.
    __syncthreads();
    MBAR_WAIT(war0 + ((NCHUNK - 1) % 3) * 8, ((NCHUNK - 1) / 3) & 1);
    TCGEN05_FENCE_AFTER();
    #pragma unroll
    for (int cb = 0; cb < T2N; cb += 32) {
        uint32_t r[32];
        LDTM_X32(r, tmem + cb);
        TCGEN05_WAIT_LD();
        float* Cp = C + (size_t)(bm + rank * 128 + wid * 32 + lid) * N + bn + cb;
        #pragma unroll
        for (int j = 0; j < 8; j++) {
            float4 v;
            v.x = __uint_as_float(r[j*4+0]); v.y = __uint_as_float(r[j*4+1]);
            v.z = __uint_as_float(r[j*4+2]); v.w = __uint_as_float(r[j*4+3]);
            *(float4*)(Cp + j * 4) = v;
        }
    }
    __syncthreads();
    CLUSTER_SYNC();
    if (wid == 0) TCGEN05_DEALLOC_CG2(tmem, 256);
}

// ---------------- flash (R10 version, passing, unchanged) ----------------
__global__ __launch_bounds__(128, 1) void flash_tc(
    const __nv_bfloat16* __restrict__ Qhi, const __nv_bfloat16* __restrict__ Qlo,
    const __nv_bfloat16* __restrict__ Khi, const __nv_bfloat16* __restrict__ Klo,
    const __nv_bfloat16* __restrict__ Vthi, const __nv_bfloat16* __restrict__ Vtlo,
    __nv_bfloat16* __restrict__ Yhi, __nv_bfloat16* __restrict__ Ylo)
{
    extern __shared__ char sm[];
    const uint32_t sbase  = smem_u32(sm);
    const uint32_t smbar  = sbase;
    const uint32_t pvmbar = sbase + 16;
    const uint32_t tptr   = sbase + 32;
    const uint32_t tile0  = (sbase + 48 + 1023) & ~1023u;

    const int tid = threadIdx.x, wid = tid >> 5;
    const int qtile = gridDim.x - 1 - blockIdx.x;
    const int h = blockIdx.y, b = blockIdx.z, kvh = h >> 2;
    const int q0 = qtile * 128;
    const int nkt = 2 * qtile + 2;
    const uint32_t woff = (uint32_t)wid << 21;
    const int row_g = q0 + tid;

    if (tid == 0) {
        MBAR_INIT(smbar, 1);  MBAR_INIT(smbar + 8, 1);
        MBAR_INIT(pvmbar, 1); MBAR_INIT(pvmbar + 8, 1);
    }
    if (wid == 0) { TCGEN05_ALLOC(tptr, 512); TCGEN05_RELINQ(); }
    __syncthreads();
    uint32_t tmem;
    asm volatile("ld.shared.b32 %0, [%1];" : "=r"(tmem) : "r"(tptr));

    {
        const char* qh = (const char*)Qhi + ((size_t)(b * SEQ + row_g) * DIM + h * HD) * 2;
        const char* ql = (const char*)Qlo + ((size_t)(b * SEQ + row_g) * DIM + h * HD) * 2;
        uint32_t r64[64];
        #pragma unroll
        for (int i = 0; i < 16; i++) {
            uint4 v = *(const uint4*)(qh + i * 16);
            r64[i*4] = v.x; r64[i*4+1] = v.y; r64[i*4+2] = v.z; r64[i*4+3] = v.w;
        }
        STTM_X32(tmem + TQHI + woff, r64);
        STTM_X32(tmem + TQHI + 32 + woff, r64 + 32);
        #pragma unroll
        for (int i = 0; i < 16; i++) {
            uint4 v = *(const uint4*)(ql + i * 16);
            r64[i*4] = v.x; r64[i*4+1] = v.y; r64[i*4+2] = v.z; r64[i*4+3] = v.w;
        }
        STTM_X32(tmem + TQLO + woff, r64);
        STTM_X32(tmem + TQLO + 32 + woff, r64 + 32);
        TCGEN05_WAIT_ST();
    }
    TCGEN05_FENCE_BEFORE();
    __syncthreads();

    const char* khbase = (const char*)Khi + (size_t)kvh * HD * 2;
    const char* klbase = (const char*)Klo + (size_t)kvh * HD * 2;
    const char* vhbase = (const char*)Vthi + ((size_t)(b * NKV + kvh) * HD) * (SEQ * 2);
    const char* vlbase = (const char*)Vtlo + ((size_t)(b * NKV + kvh) * HD) * (SEQ * 2);

    auto load_stage = [&](int kt) {
        uint32_t kh = tile0 + (kt % 3) * FL_STAGEB;
        uint32_t kl = kh + 16384, vh = kh + 32768, vl = kh + 49152;
        int k0 = kt * 64;
        #pragma unroll
        for (int i = 0; i < 8; i++) {
            int g = tid + i * 128;
            int r = g >> 4, c = g & 15;
            uint32_t d = SWZ((uint32_t)(((r >> 3) << 10) + ((c >> 3) << 13) +
                                        ((r & 7) << 7) + ((c & 7) << 4)));
            size_t so = (size_t)(b * SEQ + k0 + r) * (KVD * 2) + c * 16;
            CP_ASYNC16(kh + d, khbase + so);
            CP_ASYNC16(kl + d, klbase + so);
        }
        #pragma unroll
        for (int i = 0; i < 8; i++) {
            int g = tid + i * 128;
            int r = g >> 3, c = g & 7;
            uint32_t d = SWZ((uint32_t)(((r >> 3) << 10) + ((r & 7) << 7) + (c << 4)));
            size_t so = (size_t)r * (SEQ * 2) + (size_t)k0 * 2 + c * 16;
            CP_ASYNC16(vh + d, vhbase + so);
            CP_ASYNC16(vl + d, vlbase + so);
        }
    };

    auto issue_qk = [&](int kt) {
        uint32_t kh = tile0 + (kt % 3) * FL_STAGEB;
        uint64_t dh = mk_desc(kh), dl = mk_desc(kh + 16384);
        uint32_t dst = tmem + TS(kt & 1);
        #pragma unroll
        for (int ks = 0; ks < 8; ks++) {
            uint64_t off = (uint64_t)(((ks >> 2) << 9) + ((ks & 3) << 1));
            mma_ts(dst, tmem + TQHI + ks * 8, dh + off, IDQ, (uint32_t)(ks != 0));
        }
        #pragma unroll
        for (int ks = 0; ks < 8; ks++) {
            uint64_t off = (uint64_t)(((ks >> 2) << 9) + ((ks & 3) << 1));
            mma_ts(dst, tmem + TQLO + ks * 8, dh + off, IDQ, 1u);
        }
        #pragma unroll
        for (int ks = 0; ks < 8; ks++) {
            uint64_t off = (uint64_t)(((ks >> 2) << 9) + ((ks & 3) << 1));
            mma_ts(dst, tmem + TQHI + ks * 8, dl + off, IDQ, 1u);
        }
        TCGEN05_COMMIT(smbar + (kt & 1) * 8);
    };

    load_stage(0); CP_COMMIT();
    load_stage(1); CP_COMMIT();
    CP_WAIT(1);
    FENCE_PROXY_ASYNC();
    __syncthreads();
    if (wid == 0 && elect1()) { TCGEN05_FENCE_AFTER(); issue_qk(0); }

    float l_reg = 0.f;

    for (int kt = 0; kt < nkt; kt++) {
        const int st = kt & 1;
        if (kt >= 1) MBAR_WAIT(pvmbar + ((kt - 1) & 1) * 8, ((kt - 1) >> 1) & 1);
        if (kt + 2 < nkt) load_stage(kt + 2);
        CP_COMMIT();

        MBAR_WAIT(smbar + st * 8, (kt >> 1) & 1);
        TCGEN05_FENCE_AFTER();

        if (kt + 1 < nkt) {
            CP_WAIT(1);
            FENCE_PROXY_ASYNC();
            __syncthreads();
            if (wid == 0 && elect1()) issue_qk(kt + 1);
        }

        uint32_t sreg[64];
        LDTM_X32(sreg, tmem + TS(st));
        LDTM_X32(sreg + 32, tmem + TS(st) + 32);
        TCGEN05_WAIT_LD();

        uint32_t phi[32], plo[32];
        const int k0 = kt * 64;
        const bool diagt = (kt >= 2 * qtile);
        float l_add = 0.f;
        #pragma unroll
        for (int j2 = 0; j2 < 32; j2++) {
            float p0 = fast_ex2(__uint_as_float(sreg[2 * j2])     - B2C);
            float p1 = fast_ex2(__uint_as_float(sreg[2 * j2 + 1]) - B2C);
            if (diagt) {
                if (k0 + 2 * j2     > row_g) p0 = 0.f;
                if (k0 + 2 * j2 + 1 > row_g) p1 = 0.f;
            }
            l_add += p0 + p1;
            uint32_t h2 = pack_bf16x2(p0, p1);
            float f0 = __uint_as_float(h2 << 16);
            float f1 = __uint_as_float(h2 & 0xFFFF0000u);
            phi[j2] = h2;
            plo[j2] = pack_bf16x2(p0 - f0, p1 - f1);
        }
        l_reg += l_add;

        STTM_X32(tmem + TPH(st) + woff, phi);
        STTM_X32(tmem + TPL(st) + woff, plo);
        TCGEN05_WAIT_ST();
        TCGEN05_FENCE_BEFORE();
        __syncthreads();

        if (wid == 0 && elect1()) {
            TCGEN05_FENCE_AFTER();
            uint32_t vh = tile0 + (kt % 3) * FL_STAGEB + 32768;
            uint64_t dvh = mk_desc(vh), dvl = mk_desc(vh + 16384);
            #pragma unroll
            for (int ks = 0; ks < 4; ks++)
                mma_ts(tmem + TO, tmem + TPH(st) + ks * 8, dvh + ks * 2, IDPV,
                       (uint32_t)((kt | ks) != 0));
            #pragma unroll
            for (int ks = 0; ks < 4; ks++)
                mma_ts(tmem + TO, tmem + TPL(st) + ks * 8, dvh + ks * 2, IDPV, 1u);
            #pragma unroll
            for (int ks = 0; ks < 4; ks++)
                mma_ts(tmem + TO, tmem + TPH(st) + ks * 8, dvl + ks * 2, IDPV, 1u);
            TCGEN05_COMMIT(pvmbar + st * 8);
        }
    }

    MBAR_WAIT(pvmbar + ((nkt - 1) & 1) * 8, ((nkt - 1) >> 1) & 1);
    TCGEN05_FENCE_AFTER();
    float inv = 1.0f / l_reg;
    char* yh = (char*)Yhi + ((size_t)(b * SEQ + row_g) * DIM + h * HD) * 2;
    char* yl = (char*)Ylo + ((size_t)(b * SEQ + row_g) * DIM + h * HD) * 2;
    #pragma unroll
    for (int blk = 0; blk < 4; blk++) {
        uint32_t o[32];
        LDTM_X32(o, tmem + TO + blk * 32);
        TCGEN05_WAIT_LD();
        uint32_t ph[16], pl[16];
        #pragma unroll
        for (int j = 0; j < 16; j++) {
            float y0 = __uint_as_float(o[2 * j])     * inv;
            float y1 = __uint_as_float(o[2 * j + 1]) * inv;
            uint32_t h2 = pack_bf16x2(y0, y1);
            ph[j] = h2;
            pl[j] = pack_bf16x2(y0 - __uint_as_float(h2 << 16),
                                y1 - __uint_as_float(h2 & 0xFFFF0000u));
        }
        #pragma unroll
        for (int q = 0; q < 4; q++) {
            *(uint4*)(yh + blk * 64 + q * 16) = *(uint4*)&ph[q * 4];
            *(uint4*)(yl + blk * 64 + q * 16) = *(uint4*)&pl[q * 4];
        }
    }
    __syncthreads();
    if (wid == 0) TCGEN05_DEALLOC(tmem, 512);
}

#else  // ---- generic compute_103 fallbacks (valid, never executed) ------

__global__ __launch_bounds__(128, 1) __cluster_dims__(2, 1, 1)
void gemm2_kernel(
    float* __restrict__ C,
    const __nv_bfloat16* __restrict__ Ahi, const __nv_bfloat16* __restrict__ Alo,
    const __nv_bfloat16* __restrict__ Bhi, const __nv_bfloat16* __restrict__ Blo,
    int N)
{
    const int m = blockIdx.y * T2M + (blockIdx.x & 1) * 128 + threadIdx.x;
    const int n0 = (blockIdx.x >> 1) * T2N;
    for (int n = n0; n < n0 + T2N; n++) {
        float s = 0.f;
        for (int k = 0; k < GK; k++) {
            float a = __bfloat162float(Ahi[(size_t)m * GK + k]) +
                      __bfloat162float(Alo[(size_t)m * GK + k]);
            float b = __bfloat162float(Bhi[(size_t)n * GK + k]) +
                      __bfloat162float(Blo[(size_t)n * GK + k]);
            s = fmaf(a, b, s);
        }
        C[(size_t)m * N + n] = s;
    }
}

__global__ __launch_bounds__(128, 1) void flash_tc(
    const __nv_bfloat16* __restrict__ Qhi, const __nv_bfloat16* __restrict__ Qlo,
    const __nv_bfloat16* __restrict__ Khi, const __nv_bfloat16* __restrict__ Klo,
    const __nv_bfloat16* __restrict__ Vthi, const __nv_bfloat16* __restrict__ Vtlo,
    __nv_bfloat16* __restrict__ Yhi, __nv_bfloat16* __restrict__ Ylo)
{
    const int qtile = gridDim.x - 1 - blockIdx.x;
    const int h = blockIdx.y, b = blockIdx.z, kvh = h >> 2;
    const int row = qtile * 128 + threadIdx.x;
    float o[HD], l = 0.f;
    for (int d = 0; d < HD; d++) o[d] = 0.f;
    for (int k = 0; k <= row; k++) {
        float s = 0.f;
        size_t kb = (size_t)(b * SEQ + k) * KVD + kvh * HD;
        size_t qb = (size_t)(b * SEQ + row) * DIM + h * HD;
        for (int d = 0; d < HD; d++)
            s = fmaf(__bfloat162float(Qhi[qb + d]) + __bfloat162float(Qlo[qb + d]),
                     __bfloat162float(Khi[kb + d]) + __bfloat162float(Klo[kb + d]), s);
        float p = exp2f(s - B2C);
        l += p;
        size_t vb = ((size_t)(b * NKV + kvh) * HD) * SEQ + k;
        for (int d = 0; d < HD; d++)
            o[d] += p * (__bfloat162float(Vthi[vb + (size_t)d * SEQ]) +
                         __bfloat162float(Vtlo[vb + (size_t)d * SEQ]));
    }
    float inv = 1.0f / l;
    for (int d = 0; d < HD; d++) {
        float y = o[d] * inv;
        __nv_bfloat16 hh = __float2bfloat16(y);
        size_t idx = (size_t)(b * SEQ + row) * DIM + h * HD + d;
        Yhi[idx] = hh;
        Ylo[idx] = __float2bfloat16(y - __bfloat162float(hh));
    }
}
#endif // HAS_TCGEN05

// ---- merged split (x, Wq, Wk, Wv, Wo) + RoPE table ----------------------
#define G_X  (NTOK * DIM / 4)
#define G_WQ (DIM * DIM / 4)
#define G_WKV (KVD * DIM / 4)
#define G_TOT (G_X + G_WQ + 2 * G_WKV + G_WQ)
#define ROPE_N (SEQ * 64)

__global__ __launch_bounds__(256) void split_all_kernel(
    const float* __restrict__ x, const float* __restrict__ Wq,
    const float* __restrict__ Wk, const float* __restrict__ Wv,
    const float* __restrict__ Wo)
{
    int i = blockIdx.x * 256 + threadIdx.x;
    if (i >= G_TOT) {
        int idx = i - G_TOT;
        if (idx < ROPE_N) {
            int s = idx >> 6, d = idx & 63;
            double e = (double)(-2.0 * d / (double)HD) * 9.210340371976184;
            float invf = (float)exp(e);
            float fr = (float)s * invf;
            float c, sn;
            sincosf(fr, &sn, &c);
            g_cos[idx] = c;
            g_sin[idx] = sn;
        }
        return;
    }
    const float* src;
    __nv_bfloat16 *hi, *lo;
    int off;
    if (i < G_X) {
        src = x; hi = g_xhi; lo = g_xlo; off = i;
    } else if (i < G_X + G_WQ) {
        src = Wq; hi = g_wqkvhi; lo = g_wqkvlo; off = i - G_X;
    } else if (i < G_X + G_WQ + G_WKV) {
        src = Wk; hi = g_wqkvhi + (size_t)DIM * GK; lo = g_wqkvlo + (size_t)DIM * GK;
        off = i - (G_X + G_WQ);
    } else if (i < G_X + G_WQ + 2 * G_WKV) {
        src = Wv; hi = g_wqkvhi + (size_t)(DIM + KVD) * GK; lo = g_wqkvlo + (size_t)(DIM + KVD) * GK;
        off = i - (G_X + G_WQ + G_WKV);
    } else {
        src = Wo; hi = g_wohi; lo = g_wolo; off = i - (G_X + G_WQ + 2 * G_WKV);
    }
    float4 v = ((const float4*)src)[off];
    __nv_bfloat16 h0 = __float2bfloat16(v.x), h1 = __float2bfloat16(v.y);
    __nv_bfloat16 h2 = __float2bfloat16(v.z), h3 = __float2bfloat16(v.w);
    __nv_bfloat162* H = (__nv_bfloat162*)hi;
    __nv_bfloat162* L = (__nv_bfloat162*)lo;
    H[off*2+0] = __nv_bfloat162(h0, h1);
    H[off*2+1] = __nv_bfloat162(h2, h3);
    L[off*2+0] = __nv_bfloat162(__float2bfloat16(v.x - __bfloat162float(h0)),
                                __float2bfloat16(v.y - __bfloat162float(h1)));
    L[off*2+1] = __nv_bfloat162(__float2bfloat16(v.z - __bfloat162float(h2)),
                                __float2bfloat16(v.w - __bfloat162float(h3)));
}

__global__ __launch_bounds__(256) void vtrans_split_kernel(
    const float* __restrict__ V, int rowstride)
{
    __shared__ float t[32][33];
    const int ti = blockIdx.x, di = blockIdx.y, bk = blockIdx.z;
    const int b = bk >> 2, kvh = bk & 3;
    const int tx = threadIdx.x & 31, ty = threadIdx.x >> 5;
    #pragma unroll
    for (int i = 0; i < 4; i++) {
        int tok = ti * 32 + ty + i * 8;
        t[ty + i * 8][tx] = V[(size_t)(b * SEQ + tok) * rowstride + kvh * HD + di * 32 + tx];
    }
    __syncthreads();
    #pragma unroll
    for (int i = 0; i < 4; i++) {
        int d = di * 32 + ty + i * 8;
        float v = t[tx][ty + i * 8];
        __nv_bfloat16 hh = __float2bfloat16(v);
        size_t o = ((size_t)(bk * HD + d)) * SEQ + ti * 32 + tx;
        g_vthi[o] = hh;
        g_vtlo[o] = __float2bfloat16(v - __bfloat162float(hh));
    }
}

// merged warp-per-(token,headcombo) norm+rope+split: hc<16 -> q, else k
__global__ __launch_bounds__(256) void norm_rope_all_kernel(
    const float* __restrict__ qkv, const float* __restrict__ gain)
{
    const int idx = blockIdx.x * 8 + (threadIdx.x >> 5);
    const int lane = threadIdx.x & 31;
    const int token = idx / (NHEADS + NKV);
    const int hc = idx - token * (NHEADS + NKV);
    const int s = token & (SEQ - 1);
    const bool isq = hc < NHEADS;
    const size_t ibase = (size_t)token * QKVD + (isq ? hc * HD : DIM + (hc - NHEADS) * HD);
    const size_t obase = isq ? (size_t)token * DIM + hc * HD
                             : (size_t)token * KVD + (hc - NHEADS) * HD;
    __nv_bfloat16* hi = isq ? g_qhi : g_khi;
    __nv_bfloat16* lo = isq ? g_qlo : g_klo;

    float x0 = qkv[ibase + lane];
    float x1 = qkv[ibase + lane + 32];
    float x2 = qkv[ibase + lane + 64];
    float x3 = qkv[ibase + lane + 96];
    float ss = x0 * x0 + x1 * x1 + x2 * x2 + x3 * x3;
    #pragma unroll
    for (int o = 16; o > 0; o >>= 1) ss += __shfl_xor_sync(0xffffffffu, ss, o);
    float r = rsqrtf(ss * (1.0f / HD) + 1.1920929e-7f);
    float g = (isq ? gain[hc] * QFAC : 1.0f) * r;

    float c0 = g_cos[s * 64 + lane],      s0 = g_sin[s * 64 + lane];
    float c1 = g_cos[s * 64 + lane + 32], s1 = g_sin[s * 64 + lane + 32];
    float oa1 = (x0 * c0 + x2 * s0) * g, oa2 = (x2 * c0 - x0 * s0) * g;
    float ob1 = (x1 * c1 + x3 * s1) * g, ob2 = (x3 * c1 - x1 * s1) * g;

    __nv_bfloat16 ha1 = __float2bfloat16(oa1), ha2 = __float2bfloat16(oa2);
    __nv_bfloat16 hb1 = __float2bfloat16(ob1), hb2 = __float2bfloat16(ob2);
    hi[obase + lane]      = ha1;
    hi[obase + lane + 32] = hb1;
    hi[obase + lane + 64] = ha2;
    hi[obase + lane + 96] = hb2;
    lo[obase + lane]      = __float2bfloat16(oa1 - __bfloat162float(ha1));
    lo[obase + lane + 32] = __float2bfloat16(ob1 - __bfloat162float(hb1));
    lo[obase + lane + 64] = __float2bfloat16(oa2 - __bfloat162float(ha2));
    lo[obase + lane + 96] = __float2bfloat16(ob2 - __bfloat162float(hb2));
}

extern "C" void kernel_launch(void* const* d_in, const int* in_sizes, int n_in,
                              void* d_out, int out_size)
{
    const float* x  = (const float*)d_in[0];
    const float* Wq = (const float*)d_in[1];
    const float* Wk = (const float*)d_in[2];
    const float* Wv = (const float*)d_in[3];
    const float* Wo = (const float*)d_in[4];
    const float* qg = (const float*)d_in[5];
    float* out = (float*)d_out;

    float *qkv;
    __nv_bfloat16 *xhi, *xlo, *yhi, *ylo, *qhi, *qlo, *khi, *klo;
    __nv_bfloat16 *wqkvh, *wqkvl, *woh, *wol, *vthi, *vtlo;
    cudaGetSymbolAddress((void**)&qkv, g_qkv);
    cudaGetSymbolAddress((void**)&xhi, g_xhi);
    cudaGetSymbolAddress((void**)&xlo, g_xlo);
    cudaGetSymbolAddress((void**)&yhi, g_yhi);
    cudaGetSymbolAddress((void**)&ylo, g_ylo);
    cudaGetSymbolAddress((void**)&qhi, g_qhi);
    cudaGetSymbolAddress((void**)&qlo, g_qlo);
    cudaGetSymbolAddress((void**)&khi, g_khi);
    cudaGetSymbolAddress((void**)&klo, g_klo);
    cudaGetSymbolAddress((void**)&vthi, g_vthi);
    cudaGetSymbolAddress((void**)&vtlo, g_vtlo);
    cudaGetSymbolAddress((void**)&wqkvh, g_wqkvhi);
    cudaGetSymbolAddress((void**)&wqkvl, g_wqkvlo);
    cudaGetSymbolAddress((void**)&woh, g_wohi);
    cudaGetSymbolAddress((void**)&wol, g_wolo);

    cudaFuncSetAttribute(gemm2_kernel,
                         cudaFuncAttributeMaxDynamicSharedMemorySize, GEMM2_SMEM);
    cudaFuncSetAttribute(flash_tc,
                         cudaFuncAttributeMaxDynamicSharedMemorySize, FL_SMEM);

    split_all_kernel<<<(G_TOT + ROPE_N + 255) / 256, 256>>>(x, Wq, Wk, Wv, Wo);

    gemm2_kernel<<<dim3((QKVD / T2N) * 2, NTOK / T2M), 128, GEMM2_SMEM>>>(
        qkv, xhi, xlo, wqkvh, wqkvl, QKVD);

    norm_rope_all_kernel<<<NTOK * (NHEADS + NKV) / 8, 256>>>(qkv, qg);
    vtrans_split_kernel<<<dim3(SEQ / 32, HD / 32, BSZ * NKV), 256>>>(qkv + DIM + KVD, QKVD);

    flash_tc<<<dim3(SEQ / 128, NHEADS, BSZ), 128, FL_SMEM>>>(
        qhi, qlo, khi, klo, vthi, vtlo, yhi, ylo);

    gemm2_kernel<<<dim3((DIM / T2N) * 2, NTOK / T2M), 128, GEMM2_SMEM>>>(
        out, yhi, ylo, woh, wol, DIM);
}

// round 13
// speedup vs baseline: 1.0085x; 1.0085x over previous
#include <cuda_runtime.h>
#include <cuda_bf16.h>
#include <math.h>
#include <cstdint>

#define BSZ 4
#define SEQ 2048
#define DIM 2048
#define NHEADS 16
#define NKV 4
#define HD 128
#define KVD 512
#define NTOK (BSZ*SEQ)
#define GK 2048
#define QKVD 3072
#define QFAC (0.088388347648318447f * 1.4426950408889634f)

#if !defined(__CUDA_ARCH__) || defined(__CUDA_ARCH_FEAT_SM103_ALL) || defined(__CUDA_ARCH_FEAT_SM100_ALL)
#define HAS_TCGEN05 1
#else
#define HAS_TCGEN05 0
#endif

__device__ float g_qkv[(size_t)NTOK * KVD];            // fp32 V staging only (16 MB)
__device__ __nv_bfloat16 g_xhi[(size_t)NTOK * DIM];
__device__ __nv_bfloat16 g_xlo[(size_t)NTOK * DIM];
__device__ __nv_bfloat16 g_yhi[(size_t)NTOK * DIM];
__device__ __nv_bfloat16 g_ylo[(size_t)NTOK * DIM];
__device__ __nv_bfloat16 g_qhi[(size_t)NTOK * DIM];
__device__ __nv_bfloat16 g_qlo[(size_t)NTOK * DIM];
__device__ __nv_bfloat16 g_khi[(size_t)NTOK * KVD];
__device__ __nv_bfloat16 g_klo[(size_t)NTOK * KVD];
__device__ __nv_bfloat16 g_vthi[(size_t)NTOK * KVD];   // [b][kvh][d][SEQ]
__device__ __nv_bfloat16 g_vtlo[(size_t)NTOK * KVD];
__device__ __nv_bfloat16 g_wqkvhi[(size_t)QKVD * GK];
__device__ __nv_bfloat16 g_wqkvlo[(size_t)QKVD * GK];
__device__ __nv_bfloat16 g_wohi[(size_t)DIM * DIM];
__device__ __nv_bfloat16 g_wolo[(size_t)DIM * DIM];
__device__ float g_cos[SEQ * 64];
__device__ float g_sin[SEQ * 64];

__device__ __forceinline__ uint32_t smem_u32(const void* p) {
    uint32_t a;
    asm("{ .reg .u64 t; cvta.to.shared.u64 t, %1; cvt.u32.u64 %0, t; }" : "=r"(a) : "l"(p));
    return a;
}
#define SWZ(o) ((o) ^ (((o) >> 3) & 0x70))
#define CP_ASYNC16(dst, src) \
    asm volatile("cp.async.cg.shared.global [%0], [%1], 16;" :: "r"(dst), "l"(src) : "memory")
#define CP_COMMIT() asm volatile("cp.async.commit_group;" ::: "memory")
#define CP_WAIT(n)  asm volatile("cp.async.wait_group %0;" :: "n"(n) : "memory")
#define MBAR_INIT(a, c) \
    asm volatile("mbarrier.init.shared.b64 [%0], %1;" :: "r"(a), "r"(c) : "memory")
#define MBAR_WAIT(a, ph) do { \
    uint32_t _m = (a), _p = (ph), _d; \
    asm volatile("{\n .reg .pred p;\n mbarrier.try_wait.parity.acquire.cta.shared::cta.b64 p, [%1], %2;\n selp.b32 %0,1,0,p;\n}" \
        : "=r"(_d) : "r"(_m), "r"(_p) : "memory"); \
    if (!_d) { \
        asm volatile("{\n .reg .pred P1;\nWL%=:\n mbarrier.try_wait.parity.acquire.cta.shared::cta.b64 P1, [%0], %1, 0x989680;\n @P1 bra.uni WD%=;\n bra.uni WL%=;\nWD%=:\n}" \
            :: "r"(_m), "r"(_p) : "memory"); \
    } } while (0)
#define MBAR_ARRIVE_LEADER(a) \
    asm volatile("{\n .reg .b32 la;\n and.b32 la, %0, 0xFEFFFFFF;\n" \
        " mbarrier.arrive.shared::cluster.b64 _, [la];\n}" :: "r"(a) : "memory")
#define CLUSTER_SYNC() do { \
    asm volatile("barrier.cluster.arrive.aligned;" ::: "memory"); \
    asm volatile("barrier.cluster.wait.aligned;" ::: "memory"); } while (0)
#define FENCE_PROXY_ASYNC() asm volatile("fence.proxy.async.shared::cta;" ::: "memory")

__device__ __forceinline__ float fast_ex2(float x) {
    float r; asm("ex2.approx.ftz.f32 %0, %1;" : "=f"(r) : "f"(x)); return r;
}
__device__ __forceinline__ uint32_t pack_bf16x2(float lo, float hi) {
    uint32_t r; asm("cvt.rn.bf16x2.f32 %0, %1, %2;" : "=r"(r) : "f"(hi), "f"(lo)); return r;
}

#define T2M 256
#define T2N 256
#define NST2 3
#define NCHUNK (GK / 64)
#define ST2_BYTES (4 * 16384)
#define GEMM2_SMEM (2048 + NST2 * ST2_BYTES)
#define GEMM2_IDESC ((1u<<4) | (1u<<7) | (1u<<10) | ((T2N/8)<<17) | ((T2M/16)<<24))

#define FL_STAGEB 65536
#define FL_SMEM (2048 + 3 * FL_STAGEB)
#define TQHI 0
#define TQLO 64
#define TO   128
#define TS(st)  (256 + (st) * 64)
#define TPH(st) (384 + (st) * 64)
#define TPL(st) (384 + (st) * 64 + 32)
#define IDQ  ((1u<<4)|(1u<<7)|(1u<<10)|((64/8)<<17)|((128/16)<<24))
#define IDPV ((1u<<4)|(1u<<7)|(1u<<10)|((128/8)<<17)|((128/16)<<24))
#define B2C  17.0f

#if HAS_TCGEN05

__device__ __forceinline__ uint32_t elect1() {
    uint32_t p;
    asm volatile("{.reg .pred P; elect.sync _|P, 0xFFFFFFFF; selp.b32 %0,1,0,P;}" : "=r"(p));
    return p;
}
#define TCGEN05_ALLOC(a, n) \
    asm volatile("tcgen05.alloc.cta_group::1.sync.aligned.shared::cta.b32 [%0], %1;" :: "r"(a), "r"(n) : "memory")
#define TCGEN05_RELINQ() asm volatile("tcgen05.relinquish_alloc_permit.cta_group::1.sync.aligned;")
#define TCGEN05_DEALLOC(t, n) \
    asm volatile("tcgen05.dealloc.cta_group::1.sync.aligned.b32 %0, %1;" :: "r"(t), "r"(n))
#define TCGEN05_ALLOC_CG2(a, n) \
    asm volatile("tcgen05.alloc.cta_group::2.sync.aligned.shared::cta.b32 [%0], %1;" :: "r"(a), "r"(n) : "memory")
#define TCGEN05_RELINQ_CG2() asm volatile("tcgen05.relinquish_alloc_permit.cta_group::2.sync.aligned;")
#define TCGEN05_DEALLOC_CG2(t, n) \
    asm volatile("tcgen05.dealloc.cta_group::2.sync.aligned.b32 %0, %1;" :: "r"(t), "r"(n))
#define TCGEN05_COMMIT(m) \
    asm volatile("tcgen05.commit.cta_group::1.mbarrier::arrive::one.shared::cluster.b64 [%0];" :: "r"(m) : "memory")
#define TCGEN05_COMMIT_MC_CG2(m, mask) \
    asm volatile("tcgen05.commit.cta_group::2.mbarrier::arrive::one.shared::cluster.multicast::cluster.b64 [%0], %1;" \
        :: "r"(m), "h"((uint16_t)(mask)) : "memory")
#define TCGEN05_FENCE_BEFORE() asm volatile("tcgen05.fence::before_thread_sync;" ::: "memory")
#define TCGEN05_FENCE_AFTER()  asm volatile("tcgen05.fence::after_thread_sync;" ::: "memory")
#define TCGEN05_WAIT_LD() asm volatile("tcgen05.wait::ld.sync.aligned;" ::: "memory")
#define TCGEN05_WAIT_ST() asm volatile("tcgen05.wait::st.sync.aligned;" ::: "memory")

#define LDTM_X32(r, a) \
    asm volatile("tcgen05.ld.sync.aligned.32x32b.x32.b32 " \
        "{%0,%1,%2,%3,%4,%5,%6,%7,%8,%9,%10,%11,%12,%13,%14,%15," \
        "%16,%17,%18,%19,%20,%21,%22,%23,%24,%25,%26,%27,%28,%29,%30,%31}, [%32];" \
        : "=r"((r)[0]),"=r"((r)[1]),"=r"((r)[2]),"=r"((r)[3]),"=r"((r)[4]),"=r"((r)[5]),"=r"((r)[6]),"=r"((r)[7]), \
          "=r"((r)[8]),"=r"((r)[9]),"=r"((r)[10]),"=r"((r)[11]),"=r"((r)[12]),"=r"((r)[13]),"=r"((r)[14]),"=r"((r)[15]), \
          "=r"((r)[16]),"=r"((r)[17]),"=r"((r)[18]),"=r"((r)[19]),"=r"((r)[20]),"=r"((r)[21]),"=r"((r)[22]),"=r"((r)[23]), \
          "=r"((r)[24]),"=r"((r)[25]),"=r"((r)[26]),"=r"((r)[27]),"=r"((r)[28]),"=r"((r)[29]),"=r"((r)[30]),"=r"((r)[31]) \
        : "r"(a))
#define STTM_X32(a, r) \
    asm volatile("tcgen05.st.sync.aligned.32x32b.x32.b32 [%0], " \
        "{%1,%2,%3,%4,%5,%6,%7,%8,%9,%10,%11,%12,%13,%14,%15,%16," \
        "%17,%18,%19,%20,%21,%22,%23,%24,%25,%26,%27,%28,%29,%30,%31,%32};" \
        :: "r"(a), \
           "r"((r)[0]),"r"((r)[1]),"r"((r)[2]),"r"((r)[3]),"r"((r)[4]),"r"((r)[5]),"r"((r)[6]),"r"((r)[7]), \
           "r"((r)[8]),"r"((r)[9]),"r"((r)[10]),"r"((r)[11]),"r"((r)[12]),"r"((r)[13]),"r"((r)[14]),"r"((r)[15]), \
           "r"((r)[16]),"r"((r)[17]),"r"((r)[18]),"r"((r)[19]),"r"((r)[20]),"r"((r)[21]),"r"((r)[22]),"r"((r)[23]), \
           "r"((r)[24]),"r"((r)[25]),"r"((r)[26]),"r"((r)[27]),"r"((r)[28]),"r"((r)[29]),"r"((r)[30]),"r"((r)[31]) \
        : "memory")

__device__ __forceinline__ uint64_t mk_desc(uint32_t addr) {
    const uint64_t base = (uint64_t(2) << 61) | (uint64_t(1) << 46) |
                          (uint64_t(64) << 32) | (uint64_t(1) << 16);
    return base | ((addr >> 4) & 0x3FFF);
}
__device__ __forceinline__ void mma_ss_cg2(uint32_t d, uint64_t ad, uint64_t bd,
                                           uint32_t idesc, uint32_t en) {
    asm volatile("{\n .reg .pred p;\n setp.ne.u32 p, %5, 0;\n"
        " tcgen05.mma.cta_group::2.kind::f16 [%0], %1, %2, %3, "
        "{%4,%4,%4,%4,%4,%4,%4,%4}, p;\n}"
        :: "r"(d), "l"(ad), "l"(bd), "r"(idesc), "r"(0u), "r"(en) : "memory");
}
__device__ __forceinline__ void mma_ts(uint32_t d, uint32_t a, uint64_t bd,
                                       uint32_t idesc, uint32_t en) {
    asm volatile("{\n .reg .pred p;\n setp.ne.u32 p, %4, 0;\n"
        " tcgen05.mma.cta_group::1.kind::f16 [%0], [%1], %2, %3, {%5,%5,%5,%5}, p;\n}"
        :: "r"(d), "r"(a), "l"(bd), "r"(idesc), "r"(en), "r"(0u) : "memory");
}

// ---------------- cg2 bf16x3 GEMM, warp-specialized (R12, passing) -------
// mode 1: fused RMSNorm+RoPE+split epilogue via SMEM staging.
__global__ __launch_bounds__(128, 1) __cluster_dims__(2, 1, 1)
void gemm2_kernel(
    float* __restrict__ C,
    const __nv_bfloat16* __restrict__ Ahi, const __nv_bfloat16* __restrict__ Alo,
    const __nv_bfloat16* __restrict__ Bhi, const __nv_bfloat16* __restrict__ Blo,
    int N, int mode, const float* __restrict__ qg)
{
    extern __shared__ char sm[];
    const uint32_t sbase = smem_u32(sm);
    const uint32_t war0  = sbase + 8;
    const uint32_t full0 = sbase + 32;
    const uint32_t tile0 = (sbase + 64 + 1023) & ~1023u;
    const int tid = threadIdx.x, wid = tid >> 5, lid = tid & 31;
    const int rank = blockIdx.x & 1;
    const int bn = (blockIdx.x >> 1) * T2N;
    const int bm = blockIdx.y * T2M;

    if (tid == 0) {
        #pragma unroll
        for (int s = 0; s < NST2; s++) {
            MBAR_INIT(war0 + s * 8, 1);
            MBAR_INIT(full0 + s * 8, 192);
        }
    }
    if (wid == 0) { TCGEN05_ALLOC_CG2(sbase, 256); TCGEN05_RELINQ_CG2(); }
    __syncthreads();
    uint32_t tmem;
    asm volatile("ld.shared.b32 %0, [%1];" : "=r"(tmem) : "r"(sbase));
    CLUSTER_SYNC();

    if (wid >= 1) {
        const int lt = tid - 32;
        const char* Abase = (const char*)Ahi + (size_t)(bm + rank * 128) * (GK * 2);
        const char* Albase = (const char*)Alo + (size_t)(bm + rank * 128) * (GK * 2);
        const char* Bbase = (const char*)Bhi + (size_t)(bn + rank * 128) * (GK * 2);
        const char* Blbase = (const char*)Blo + (size_t)(bn + rank * 128) * (GK * 2);
        auto load_chunk = [&](int c) {
            uint32_t st = tile0 + (c % 3) * ST2_BYTES;
            #pragma unroll
            for (int i = 0; i < 11; i++) {
                int g = lt + i * 96;
                if (g < 1024) {
                    int row = g >> 3, seg = g & 7;
                    uint32_t so = SWZ((uint32_t)(row * 128 + seg * 16));
                    size_t go = (size_t)row * (GK * 2) + c * 128 + seg * 16;
                    CP_ASYNC16(st + so,         Abase + go);
                    CP_ASYNC16(st + 16384 + so, Albase + go);
                    CP_ASYNC16(st + 32768 + so, Bbase + go);
                    CP_ASYNC16(st + 49152 + so, Blbase + go);
                }
            }
        };
        load_chunk(0); CP_COMMIT();
        load_chunk(1); CP_COMMIT();
        for (int c = 0; c < NCHUNK; c++) {
            const int cl = c + 2;
            if (cl < NCHUNK) {
                if (cl >= NST2) MBAR_WAIT(war0 + (cl % 3) * 8, ((cl / 3) + 1) & 1);
                load_chunk(cl);
            }
            CP_COMMIT();
            CP_WAIT(2);
            FENCE_PROXY_ASYNC();
            MBAR_ARRIVE_LEADER(full0 + (c % 3) * 8);
        }
    } else if (rank == 0 && elect1()) {
        for (int c = 0; c < NCHUNK; c++) {
            MBAR_WAIT(full0 + (c % 3) * 8, (c / 3) & 1);
            uint32_t st = tile0 + (c % 3) * ST2_BYTES;
            uint64_t adh = mk_desc(st),         adl = mk_desc(st + 16384);
            uint64_t bdh = mk_desc(st + 32768), bdl = mk_desc(st + 49152);
            #pragma unroll
            for (int s = 0; s < 4; s++)
                mma_ss_cg2(tmem, adh + s * 2, bdh + s * 2, GEMM2_IDESC,
                           (uint32_t)((c | s) != 0));
            #pragma unroll
            for (int s = 0; s < 4; s++)
                mma_ss_cg2(tmem, adl + s * 2, bdh + s * 2, GEMM2_IDESC, 1u);
            #pragma unroll
            for (int s = 0; s < 4; s++)
                mma_ss_cg2(tmem, adh + s * 2, bdl + s * 2, GEMM2_IDESC, 1u);
            TCGEN05_COMMIT_MC_CG2(war0 + (c % 3) * 8, 0x3);
        }
    }

    // Sync first (parity correctness, see R12), then wait final commit.
    __syncthreads();
    MBAR_WAIT(war0 + ((NCHUNK - 1) % 3) * 8, ((NCHUNK - 1) / 3) & 1);
    TCGEN05_FENCE_AFTER();

    if (mode == 0) {
        #pragma unroll
        for (int cb = 0; cb < T2N; cb += 32) {
            uint32_t r[32];
            LDTM_X32(r, tmem + cb);
            TCGEN05_WAIT_LD();
            float* Cp = C + (size_t)(bm + rank * 128 + wid * 32 + lid) * N + bn + cb;
            #pragma unroll
            for (int j = 0; j < 8; j++) {
                float4 v;
                v.x = __uint_as_float(r[j*4+0]); v.y = __uint_as_float(r[j*4+1]);
                v.z = __uint_as_float(r[j*4+2]); v.w = __uint_as_float(r[j*4+3]);
                *(float4*)(Cp + j * 4) = v;
            }
        }
    } else {
        // ---- fused QKV epilogue: stage 128 cols at a time through SMEM ----
        char* smc = sm + (tile0 - sbase);
        float* smf = (float*)smc;                    // [128][129], conflict-free
        float* rng = (float*)(smc + 128 * 129 * 4);  // [128] rnorm * gain
        const int lrow0 = wid * 32 + lid;
        for (int hh = 0; hh < 2; hh++) {
            #pragma unroll
            for (int q = 0; q < 4; q++) {
                uint32_t r[32];
                LDTM_X32(r, tmem + hh * 128 + q * 32);
                TCGEN05_WAIT_LD();
                #pragma unroll
                for (int j = 0; j < 32; j++)
                    smf[lrow0 * 129 + q * 32 + j] = __uint_as_float(r[j]);
            }
            __syncthreads();
            const int head = (bn + hh * 128) >> 7;
            if (head < NHEADS + NKV) {
                const bool isq = head < NHEADS;
                {   // phase 1: thread-per-row sum of squares
                    const float* rp = smf + tid * 129;
                    float ss = 0.f;
                    #pragma unroll 16
                    for (int c = 0; c < 128; c++) { float v = rp[c]; ss = fmaf(v, v, ss); }
                    float rr = rsqrtf(ss * (1.0f / HD) + 1.1920929e-7f);
                    rng[tid] = (isq ? qg[head] * QFAC : 1.0f) * rr;
                }
                __syncthreads();
                __nv_bfloat16* hip = isq ? g_qhi : g_khi;
                __nv_bfloat16* lop = isq ? g_qlo : g_klo;
                for (int rr2 = 0; rr2 < 32; rr2++) {
                    int row = wid * 32 + rr2;
                    int tok = bm + rank * 128 + row;
                    int srow = tok & (SEQ - 1);
                    float g = rng[row];
                    float x0 = smf[row * 129 + lid];
                    float x1 = smf[row * 129 + lid + 32];
                    float x2 = smf[row * 129 + lid + 64];
                    float x3 = smf[row * 129 + lid + 96];
                    float c0 = g_cos[srow * 64 + lid],      s0 = g_sin[srow * 64 + lid];
                    float c1 = g_cos[srow * 64 + lid + 32], s1 = g_sin[srow * 64 + lid + 32];
                    float oa1 = (x0 * c0 + x2 * s0) * g, oa2 = (x2 * c0 - x0 * s0) * g;
                    float ob1 = (x1 * c1 + x3 * s1) * g, ob2 = (x3 * c1 - x1 * s1) * g;
                    size_t ob = isq ? (size_t)tok * DIM + head * HD
                                    : (size_t)tok * KVD + (head - NHEADS) * HD;
                    __nv_bfloat16 ha1 = __float2bfloat16(oa1), ha2 = __float2bfloat16(oa2);
                    __nv_bfloat16 hb1 = __float2bfloat16(ob1), hb2 = __float2bfloat16(ob2);
                    hip[ob + lid]      = ha1;
                    hip[ob + lid + 32] = hb1;
                    hip[ob + lid + 64] = ha2;
                    hip[ob + lid + 96] = hb2;
                    lop[ob + lid]      = __float2bfloat16(oa1 - __bfloat162float(ha1));
                    lop[ob + lid + 32] = __float2bfloat16(ob1 - __bfloat162float(hb1));
                    lop[ob + lid + 64] = __float2bfloat16(oa2 - __bfloat162float(ha2));
                    lop[ob + lid + 96] = __float2bfloat16(ob2 - __bfloat162float(hb2));
                }
            } else {
                // v heads: coalesced fp32 copy into vbuf (C), row layout [tok][KVD]
                for (int rr2 = 0; rr2 < 32; rr2++) {
                    int row = wid * 32 + rr2;
                    int tok = bm + rank * 128 + row;
                    float* vp = C + (size_t)tok * KVD + (head - NHEADS - NKV) * HD;
                    vp[lid]      = smf[row * 129 + lid];
                    vp[lid + 32] = smf[row * 129 + lid + 32];
                    vp[lid + 64] = smf[row * 129 + lid + 64];
                    vp[lid + 96] = smf[row * 129 + lid + 96];
                }
            }
            __syncthreads();
        }
    }
    __syncthreads();
    CLUSTER_SYNC();
    if (wid == 0) TCGEN05_DEALLOC_CG2(tmem, 256);
}

// ---------------- flash (R12 version, passing, unchanged) ----------------
__global__ __launch_bounds__(128, 1) void flash_tc(
    const __nv_bfloat16* __restrict__ Qhi, const __nv_bfloat16* __restrict__ Qlo,
    const __nv_bfloat16* __restrict__ Khi, const __nv_bfloat16* __restrict__ Klo,
    const __nv_bfloat16* __restrict__ Vthi, const __nv_bfloat16* __restrict__ Vtlo,
    __nv_bfloat16* __restrict__ Yhi, __nv_bfloat16* __restrict__ Ylo)
{
    extern __shared__ char sm[];
    const uint32_t sbase  = smem_u32(sm);
    const uint32_t smbar  = sbase;
    const uint32_t pvmbar = sbase + 16;
    const uint32_t tptr   = sbase + 32;
    const uint32_t tile0  = (sbase + 48 + 1023) & ~1023u;

    const int tid = threadIdx.x, wid = tid >> 5;
    const int qtile = gridDim.x - 1 - blockIdx.x;
    const int h = blockIdx.y, b = blockIdx.z, kvh = h >> 2;
    const int q0 = qtile * 128;
    const int nkt = 2 * qtile + 2;
    const uint32_t woff = (uint32_t)wid << 21;
    const int row_g = q0 + tid;

    if (tid == 0) {
        MBAR_INIT(smbar, 1);  MBAR_INIT(smbar + 8, 1);
        MBAR_INIT(pvmbar, 1); MBAR_INIT(pvmbar + 8, 1);
    }
    if (wid == 0) { TCGEN05_ALLOC(tptr, 512); TCGEN05_RELINQ(); }
    __syncthreads();
    uint32_t tmem;
    asm volatile("ld.shared.b32 %0, [%1];" : "=r"(tmem) : "r"(tptr));

    {
        const char* qh = (const char*)Qhi + ((size_t)(b * SEQ + row_g) * DIM + h * HD) * 2;
        const char* ql = (const char*)Qlo + ((size_t)(b * SEQ + row_g) * DIM + h * HD) * 2;
        uint32_t r64[64];
        #pragma unroll
        for (int i = 0; i < 16; i++) {
            uint4 v = *(const uint4*)(qh + i * 16);
            r64[i*4] = v.x; r64[i*4+1] = v.y; r64[i*4+2] = v.z; r64[i*4+3] = v.w;
        }
        STTM_X32(tmem + TQHI + woff, r64);
        STTM_X32(tmem + TQHI + 32 + woff, r64 + 32);
        #pragma unroll
        for (int i = 0; i < 16; i++) {
            uint4 v = *(const uint4*)(ql + i * 16);
            r64[i*4] = v.x; r64[i*4+1] = v.y; r64[i*4+2] = v.z; r64[i*4+3] = v.w;
        }
        STTM_X32(tmem + TQLO + woff, r64);
        STTM_X32(tmem + TQLO + 32 + woff, r64 + 32);
        TCGEN05_WAIT_ST();
    }
    TCGEN05_FENCE_BEFORE();
    __syncthreads();

    const char* khbase = (const char*)Khi + (size_t)kvh * HD * 2;
    const char* klbase = (const char*)Klo + (size_t)kvh * HD * 2;
    const char* vhbase = (const char*)Vthi + ((size_t)(b * NKV + kvh) * HD) * (SEQ * 2);
    const char* vlbase = (const char*)Vtlo + ((size_t)(b * NKV + kvh) * HD) * (SEQ * 2);

    auto load_stage = [&](int kt) {
        uint32_t kh = tile0 + (kt % 3) * FL_STAGEB;
        uint32_t kl = kh + 16384, vh = kh + 32768, vl = kh + 49152;
        int k0 = kt * 64;
        #pragma unroll
        for (int i = 0; i < 8; i++) {
            int g = tid + i * 128;
            int r = g >> 4, c = g & 15;
            uint32_t d = SWZ((uint32_t)(((r >> 3) << 10) + ((c >> 3) << 13) +
                                        ((r & 7) << 7) + ((c & 7) << 4)));
            size_t so = (size_t)(b * SEQ + k0 + r) * (KVD * 2) + c * 16;
            CP_ASYNC16(kh + d, khbase + so);
            CP_ASYNC16(kl + d, klbase + so);
        }
        #pragma unroll
        for (int i = 0; i < 8; i++) {
            int g = tid + i * 128;
            int r = g >> 3, c = g & 7;
            uint32_t d = SWZ((uint32_t)(((r >> 3) << 10) + ((r & 7) << 7) + (c << 4)));
            size_t so = (size_t)r * (SEQ * 2) + (size_t)k0 * 2 + c * 16;
            CP_ASYNC16(vh + d, vhbase + so);
            CP_ASYNC16(vl + d, vlbase + so);
        }
    };

    auto issue_qk = [&](int kt) {
        uint32_t kh = tile0 + (kt % 3) * FL_STAGEB;
        uint64_t dh = mk_desc(kh), dl = mk_desc(kh + 16384);
        uint32_t dst = tmem + TS(kt & 1);
        #pragma unroll
        for (int ks = 0; ks < 8; ks++) {
            uint64_t off = (uint64_t)(((ks >> 2) << 9) + ((ks & 3) << 1));
            mma_ts(dst, tmem + TQHI + ks * 8, dh + off, IDQ, (uint32_t)(ks != 0));
        }
        #pragma unroll
        for (int ks = 0; ks < 8; ks++) {
            uint64_t off = (uint64_t)(((ks >> 2) << 9) + ((ks & 3) << 1));
            mma_ts(dst, tmem + TQLO + ks * 8, dh + off, IDQ, 1u);
        }
        #pragma unroll
        for (int ks = 0; ks < 8; ks++) {
            uint64_t off = (uint64_t)(((ks >> 2) << 9) + ((ks & 3) << 1));
            mma_ts(dst, tmem + TQHI + ks * 8, dl + off, IDQ, 1u);
        }
        TCGEN05_COMMIT(smbar + (kt & 1) * 8);
    };

    load_stage(0); CP_COMMIT();
    load_stage(1); CP_COMMIT();
    CP_WAIT(1);
    FENCE_PROXY_ASYNC();
    __syncthreads();
    if (wid == 0 && elect1()) { TCGEN05_FENCE_AFTER(); issue_qk(0); }

    float l_reg = 0.f;

    for (int kt = 0; kt < nkt; kt++) {
        const int st = kt & 1;
        if (kt >= 1) MBAR_WAIT(pvmbar + ((kt - 1) & 1) * 8, ((kt - 1) >> 1) & 1);
        if (kt + 2 < nkt) load_stage(kt + 2);
        CP_COMMIT();

        MBAR_WAIT(smbar + st * 8, (kt >> 1) & 1);
        TCGEN05_FENCE_AFTER();

        if (kt + 1 < nkt) {
            CP_WAIT(1);
            FENCE_PROXY_ASYNC();
            __syncthreads();
            if (wid == 0 && elect1()) issue_qk(kt + 1);
        }

        uint32_t sreg[64];
        LDTM_X32(sreg, tmem + TS(st));
        LDTM_X32(sreg + 32, tmem + TS(st) + 32);
        TCGEN05_WAIT_LD();

        uint32_t phi[32], plo[32];
        const int k0 = kt * 64;
        const bool diagt = (kt >= 2 * qtile);
        float l_add = 0.f;
        #pragma unroll
        for (int j2 = 0; j2 < 32; j2++) {
            float p0 = fast_ex2(__uint_as_float(sreg[2 * j2])     - B2C);
            float p1 = fast_ex2(__uint_as_float(sreg[2 * j2 + 1]) - B2C);
            if (diagt) {
                if (k0 + 2 * j2     > row_g) p0 = 0.f;
                if (k0 + 2 * j2 + 1 > row_g) p1 = 0.f;
            }
            l_add += p0 + p1;
            uint32_t h2 = pack_bf16x2(p0, p1);
            float f0 = __uint_as_float(h2 << 16);
            float f1 = __uint_as_float(h2 & 0xFFFF0000u);
            phi[j2] = h2;
            plo[j2] = pack_bf16x2(p0 - f0, p1 - f1);
        }
        l_reg += l_add;

        STTM_X32(tmem + TPH(st) + woff, phi);
        STTM_X32(tmem + TPL(st) + woff, plo);
        TCGEN05_WAIT_ST();
        TCGEN05_FENCE_BEFORE();
        __syncthreads();

        if (wid == 0 && elect1()) {
            TCGEN05_FENCE_AFTER();
            uint32_t vh = tile0 + (kt % 3) * FL_STAGEB + 32768;
            uint64_t dvh = mk_desc(vh), dvl = mk_desc(vh + 16384);
            #pragma unroll
            for (int ks = 0; ks < 4; ks++)
                mma_ts(tmem + TO, tmem + TPH(st) + ks * 8, dvh + ks * 2, IDPV,
                       (uint32_t)((kt | ks) != 0));
            #pragma unroll
            for (int ks = 0; ks < 4; ks++)
                mma_ts(tmem + TO, tmem + TPL(st) + ks * 8, dvh + ks * 2, IDPV, 1u);
            #pragma unroll
            for (int ks = 0; ks < 4; ks++)
                mma_ts(tmem + TO, tmem + TPH(st) + ks * 8, dvl + ks * 2, IDPV, 1u);
            TCGEN05_COMMIT(pvmbar + st * 8);
        }
    }

    MBAR_WAIT(pvmbar + ((nkt - 1) & 1) * 8, ((nkt - 1) >> 1) & 1);
    TCGEN05_FENCE_AFTER();
    float inv = 1.0f / l_reg;
    char* yh = (char*)Yhi + ((size_t)(b * SEQ + row_g) * DIM + h * HD) * 2;
    char* yl = (char*)Ylo + ((size_t)(b * SEQ + row_g) * DIM + h * HD) * 2;
    #pragma unroll
    for (int blk = 0; blk < 4; blk++) {
        uint32_t o[32];
        LDTM_X32(o, tmem + TO + blk * 32);
        TCGEN05_WAIT_LD();
        uint32_t ph[16], pl[16];
        #pragma unroll
        for (int j = 0; j < 16; j++) {
            float y0 = __uint_as_float(o[2 * j])     * inv;
            float y1 = __uint_as_float(o[2 * j + 1]) * inv;
            uint32_t h2 = pack_bf16x2(y0, y1);
            ph[j] = h2;
            pl[j] = pack_bf16x2(y0 - __uint_as_float(h2 << 16),
                                y1 - __uint_as_float(h2 & 0xFFFF0000u));
        }
        #pragma unroll
        for (int q = 0; q < 4; q++) {
            *(uint4*)(yh + blk * 64 + q * 16) = *(uint4*)&ph[q * 4];
            *(uint4*)(yl + blk * 64 + q * 16) = *(uint4*)&pl[q * 4];
        }
    }
    __syncthreads();
    if (wid == 0) TCGEN05_DEALLOC(tmem, 512);
}

#else  // ---- generic compute_103 fallbacks (valid, never executed) ------

__global__ __launch_bounds__(128, 1) __cluster_dims__(2, 1, 1)
void gemm2_kernel(
    float* __restrict__ C,
    const __nv_bfloat16* __restrict__ Ahi, const __nv_bfloat16* __restrict__ Alo,
    const __nv_bfloat16* __restrict__ Bhi, const __nv_bfloat16* __restrict__ Blo,
    int N, int mode, const float* __restrict__ qg)
{
    const int m = blockIdx.y * T2M + (blockIdx.x & 1) * 128 + threadIdx.x;
    const int n0 = (blockIdx.x >> 1) * T2N;
    float row[T2N];
    for (int n = 0; n < T2N; n++) {
        float s = 0.f;
        for (int k = 0; k < GK; k++) {
            float a = __bfloat162float(Ahi[(size_t)m * GK + k]) +
                      __bfloat162float(Alo[(size_t)m * GK + k]);
            float b = __bfloat162float(Bhi[(size_t)(n0 + n) * GK + k]) +
                      __bfloat162float(Blo[(size_t)(n0 + n) * GK + k]);
            s = fmaf(a, b, s);
        }
        row[n] = s;
    }
    if (mode == 0) {
        for (int n = 0; n < T2N; n++) C[(size_t)m * N + n0 + n] = row[n];
        return;
    }
    const int srow = m & (SEQ - 1);
    for (int hh = 0; hh < 2; hh++) {
        const float* f = row + hh * 128;
        int head = (n0 + hh * 128) >> 7;
        if (head < NHEADS + NKV) {
            float ss = 0.f;
            for (int d = 0; d < 128; d++) ss += f[d] * f[d];
            float rr = rsqrtf(ss * (1.0f / HD) + 1.1920929e-7f);
            bool isq = head < NHEADS;
            float g = (isq ? qg[head] * QFAC : 1.0f) * rr;
            __nv_bfloat16* hip = isq ? g_qhi : g_khi;
            __nv_bfloat16* lop = isq ? g_qlo : g_klo;
            size_t ob = isq ? (size_t)m * DIM + head * HD
                            : (size_t)m * KVD + (head - NHEADS) * HD;
            for (int o = 0; o < 128; o++) {
                int d = o & 63;
                float c = g_cos[srow * 64 + d], sn = g_sin[srow * 64 + d];
                float x1 = f[d], x2 = f[d + 64];
                float v = ((o < 64) ? (x1 * c + x2 * sn) : (x2 * c - x1 * sn)) * g;
                __nv_bfloat16 hv = __float2bfloat16(v);
                hip[ob + o] = hv;
                lop[ob + o] = __float2bfloat16(v - __bfloat162float(hv));
            }
        } else {
            for (int d = 0; d < 128; d++)
                C[(size_t)m * KVD + (head - NHEADS - NKV) * HD + d] = f[d];
        }
    }
}

__global__ __launch_bounds__(128, 1) void flash_tc(
    const __nv_bfloat16* __restrict__ Qhi, const __nv_bfloat16* __restrict__ Qlo,
    const __nv_bfloat16* __restrict__ Khi, const __nv_bfloat16* __restrict__ Klo,
    const __nv_bfloat16* __restrict__ Vthi, const __nv_bfloat16* __restrict__ Vtlo,
    __nv_bfloat16* __restrict__ Yhi, __nv_bfloat16* __restrict__ Ylo)
{
    const int qtile = gridDim.x - 1 - blockIdx.x;
    const int h = blockIdx.y, b = blockIdx.z, kvh = h >> 2;
    const int row = qtile * 128 + threadIdx.x;
    float o[HD], l = 0.f;
    for (int d = 0; d < HD; d++) o[d] = 0.f;
    for (int k = 0; k <= row; k++) {
        float s = 0.f;
        size_t kb = (size_t)(b * SEQ + k) * KVD + kvh * HD;
        size_t qb = (size_t)(b * SEQ + row) * DIM + h * HD;
        for (int d = 0; d < HD; d++)
            s = fmaf(__bfloat162float(Qhi[qb + d]) + __bfloat162float(Qlo[qb + d]),
                     __bfloat162float(Khi[kb + d]) + __bfloat162float(Klo[kb + d]), s);
        float p = exp2f(s - B2C);
        l += p;
        size_t vb = ((size_t)(b * NKV + kvh) * HD) * SEQ + k;
        for (int d = 0; d < HD; d++)
            o[d] += p * (__bfloat162float(Vthi[vb + (size_t)d * SEQ]) +
                         __bfloat162float(Vtlo[vb + (size_t)d * SEQ]));
    }
    float inv = 1.0f / l;
    for (int d = 0; d < HD; d++) {
        float y = o[d] * inv;
        __nv_bfloat16 hh = __float2bfloat16(y);
        size_t idx = (size_t)(b * SEQ + row) * DIM + h * HD + d;
        Yhi[idx] = hh;
        Ylo[idx] = __float2bfloat16(y - __bfloat162float(hh));
    }
}
#endif // HAS_TCGEN05

// ---- merged split (x, Wq, Wk, Wv, Wo) + RoPE table ----------------------
#define G_X  (NTOK * DIM / 4)
#define G_WQ (DIM * DIM / 4)
#define G_WKV (KVD * DIM / 4)
#define G_TOT (G_X + G_WQ + 2 * G_WKV + G_WQ)
#define ROPE_N (SEQ * 64)

__global__ __launch_bounds__(256) void split_all_kernel(
    const float* __restrict__ x, const float* __restrict__ Wq,
    const float* __restrict__ Wk, const float* __restrict__ Wv,
    const float* __restrict__ Wo)
{
    int i = blockIdx.x * 256 + threadIdx.x;
    if (i >= G_TOT) {
        int idx = i - G_TOT;
        if (idx < ROPE_N) {
            int s = idx >> 6, d = idx & 63;
            double e = (double)(-2.0 * d / (double)HD) * 9.210340371976184;
            float invf = (float)exp(e);
            float fr = (float)s * invf;
            float c, sn;
            sincosf(fr, &sn, &c);
            g_cos[idx] = c;
            g_sin[idx] = sn;
        }
        return;
    }
    const float* src;
    __nv_bfloat16 *hi, *lo;
    int off;
    if (i < G_X) {
        src = x; hi = g_xhi; lo = g_xlo; off = i;
    } else if (i < G_X + G_WQ) {
        src = Wq; hi = g_wqkvhi; lo = g_wqkvlo; off = i - G_X;
    } else if (i < G_X + G_WQ + G_WKV) {
        src = Wk; hi = g_wqkvhi + (size_t)DIM * GK; lo = g_wqkvlo + (size_t)DIM * GK;
        off = i - (G_X + G_WQ);
    } else if (i < G_X + G_WQ + 2 * G_WKV) {
        src = Wv; hi = g_wqkvhi + (size_t)(DIM + KVD) * GK; lo = g_wqkvlo + (size_t)(DIM + KVD) * GK;
        off = i - (G_X + G_WQ + G_WKV);
    } else {
        src = Wo; hi = g_wohi; lo = g_wolo; off = i - (G_X + G_WQ + 2 * G_WKV);
    }
    float4 v = ((const float4*)src)[off];
    __nv_bfloat16 h0 = __float2bfloat16(v.x), h1 = __float2bfloat16(v.y);
    __nv_bfloat16 h2 = __float2bfloat16(v.z), h3 = __float2bfloat16(v.w);
    __nv_bfloat162* H = (__nv_bfloat162*)hi;
    __nv_bfloat162* L = (__nv_bfloat162*)lo;
    H[off*2+0] = __nv_bfloat162(h0, h1);
    H[off*2+1] = __nv_bfloat162(h2, h3);
    L[off*2+0] = __nv_bfloat162(__float2bfloat16(v.x - __bfloat162float(h0)),
                                __float2bfloat16(v.y - __bfloat162float(h1)));
    L[off*2+1] = __nv_bfloat162(__float2bfloat16(v.z - __bfloat162float(h2)),
                                __float2bfloat16(v.w - __bfloat162float(h3)));
}

__global__ __launch_bounds__(256) void vtrans_split_kernel(
    const float* __restrict__ V, int rowstride)
{
    __shared__ float t[32][33];
    const int ti = blockIdx.x, di = blockIdx.y, bk = blockIdx.z;
    const int b = bk >> 2, kvh = bk & 3;
    const int tx = threadIdx.x & 31, ty = threadIdx.x >> 5;
    #pragma unroll
    for (int i = 0; i < 4; i++) {
        int tok = ti * 32 + ty + i * 8;
        t[ty + i * 8][tx] = V[(size_t)(b * SEQ + tok) * rowstride + kvh * HD + di * 32 + tx];
    }
    __syncthreads();
    #pragma unroll
    for (int i = 0; i < 4; i++) {
        int d = di * 32 + ty + i * 8;
        float v = t[tx][ty + i * 8];
        __nv_bfloat16 hh = __float2bfloat16(v);
        size_t o = ((size_t)(bk * HD + d)) * SEQ + ti * 32 + tx;
        g_vthi[o] = hh;
        g_vtlo[o] = __float2bfloat16(v - __bfloat162float(hh));
    }
}

extern "C" void kernel_launch(void* const* d_in, const int* in_sizes, int n_in,
                              void* d_out, int out_size)
{
    const float* x  = (const float*)d_in[0];
    const float* Wq = (const float*)d_in[1];
    const float* Wk = (const float*)d_in[2];
    const float* Wv = (const float*)d_in[3];
    const float* Wo = (const float*)d_in[4];
    const float* qg = (const float*)d_in[5];
    float* out = (float*)d_out;

    float *vbuf;
    __nv_bfloat16 *xhi, *xlo, *yhi, *ylo, *qhi, *qlo, *khi, *klo;
    __nv_bfloat16 *wqkvh, *wqkvl, *woh, *wol, *vthi, *vtlo;
    cudaGetSymbolAddress((void**)&vbuf, g_qkv);
    cudaGetSymbolAddress((void**)&xhi, g_xhi);
    cudaGetSymbolAddress((void**)&xlo, g_xlo);
    cudaGetSymbolAddress((void**)&yhi, g_yhi);
    cudaGetSymbolAddress((void**)&ylo, g_ylo);
    cudaGetSymbolAddress((void**)&qhi, g_qhi);
    cudaGetSymbolAddress((void**)&qlo, g_qlo);
    cudaGetSymbolAddress((void**)&khi, g_khi);
    cudaGetSymbolAddress((void**)&klo, g_klo);
    cudaGetSymbolAddress((void**)&vthi, g_vthi);
    cudaGetSymbolAddress((void**)&vtlo, g_vtlo);
    cudaGetSymbolAddress((void**)&wqkvh, g_wqkvhi);
    cudaGetSymbolAddress((void**)&wqkvl, g_wqkvlo);
    cudaGetSymbolAddress((void**)&woh, g_wohi);
    cudaGetSymbolAddress((void**)&wol, g_wolo);

    cudaFuncSetAttribute(gemm2_kernel,
                         cudaFuncAttributeMaxDynamicSharedMemorySize, GEMM2_SMEM);
    cudaFuncSetAttribute(flash_tc,
                         cudaFuncAttributeMaxDynamicSharedMemorySize, FL_SMEM);

    split_all_kernel<<<(G_TOT + ROPE_N + 255) / 256, 256>>>(x, Wq, Wk, Wv, Wo);

    // merged QKV projection with fused norm+rope+split epilogue (mode 1)
    gemm2_kernel<<<dim3((QKVD / T2N) * 2, NTOK / T2M), 128, GEMM2_SMEM>>>(
        vbuf, xhi, xlo, wqkvh, wqkvl, QKVD, 1, qg);

    vtrans_split_kernel<<<dim3(SEQ / 32, HD / 32, BSZ * NKV), 256>>>(vbuf, KVD);

    flash_tc<<<dim3(SEQ / 128, NHEADS, BSZ), 128, FL_SMEM>>>(
        qhi, qlo, khi, klo, vthi, vtlo, yhi, ylo);

    // output projection (mode 0)
    gemm2_kernel<<<dim3((DIM / T2N) * 2, NTOK / T2M), 128, GEMM2_SMEM>>>(
        out, yhi, ylo, woh, wol, DIM, 0, qg);
}

// round 15
// speedup vs baseline: 1.0344x; 1.0257x over previous
#include <cuda_runtime.h>
#include <cuda_bf16.h>
#include <math.h>
#include <cstdint>

#define BSZ 4
#define SEQ 2048
#define DIM 2048
#define NHEADS 16
#define NKV 4
#define HD 128
#define KVD 512
#define NTOK (BSZ*SEQ)
#define GK 2048
#define QKVD 3072
#define QFAC (0.088388347648318447f * 1.4426950408889634f)

#if !defined(__CUDA_ARCH__) || defined(__CUDA_ARCH_FEAT_SM103_ALL) || defined(__CUDA_ARCH_FEAT_SM100_ALL)
#define HAS_TCGEN05 1
#else
#define HAS_TCGEN05 0
#endif

__device__ float g_qkv[(size_t)NTOK * KVD];            // fp32 V staging (16 MB)
__device__ __nv_bfloat16 g_xhi[(size_t)NTOK * DIM];
__device__ __nv_bfloat16 g_xlo[(size_t)NTOK * DIM];
__device__ __nv_bfloat16 g_yhi[(size_t)NTOK * DIM];
__device__ __nv_bfloat16 g_ylo[(size_t)NTOK * DIM];
__device__ __nv_bfloat16 g_qhi[(size_t)NTOK * DIM];
__device__ __nv_bfloat16 g_qlo[(size_t)NTOK * DIM];
__device__ __nv_bfloat16 g_khi[(size_t)NTOK * KVD];
__device__ __nv_bfloat16 g_klo[(size_t)NTOK * KVD];
__device__ __nv_bfloat16 g_vthi[(size_t)NTOK * KVD];   // [b][kvh][d][SEQ]
__device__ __nv_bfloat16 g_vtlo[(size_t)NTOK * KVD];
__device__ __nv_bfloat16 g_wqkvhi[(size_t)QKVD * GK];
__device__ __nv_bfloat16 g_wqkvlo[(size_t)QKVD * GK];
__device__ __nv_bfloat16 g_wohi[(size_t)DIM * DIM];
__device__ __nv_bfloat16 g_wolo[(size_t)DIM * DIM];
__device__ float g_cos[SEQ * 64];
__device__ float g_sin[SEQ * 64];

__device__ __forceinline__ uint32_t smem_u32(const void* p) {
    uint32_t a;
    asm("{ .reg .u64 t; cvta.to.shared.u64 t, %1; cvt.u32.u64 %0, t; }" : "=r"(a) : "l"(p));
    return a;
}
#define SWZ(o) ((o) ^ (((o) >> 3) & 0x70))
#define CP_ASYNC16(dst, src) \
    asm volatile("cp.async.cg.shared.global [%0], [%1], 16;" :: "r"(dst), "l"(src) : "memory")
#define CP_COMMIT() asm volatile("cp.async.commit_group;" ::: "memory")
#define CP_WAIT(n)  asm volatile("cp.async.wait_group %0;" :: "n"(n) : "memory")
#define MBAR_INIT(a, c) \
    asm volatile("mbarrier.init.shared.b64 [%0], %1;" :: "r"(a), "r"(c) : "memory")
#define MBAR_WAIT(a, ph) do { \
    uint32_t _m = (a), _p = (ph), _d; \
    asm volatile("{\n .reg .pred p;\n mbarrier.try_wait.parity.acquire.cta.shared::cta.b64 p, [%1], %2;\n selp.b32 %0,1,0,p;\n}" \
        : "=r"(_d) : "r"(_m), "r"(_p) : "memory"); \
    if (!_d) { \
        asm volatile("{\n .reg .pred P1;\nWL%=:\n mbarrier.try_wait.parity.acquire.cta.shared::cta.b64 P1, [%0], %1, 0x989680;\n @P1 bra.uni WD%=;\n bra.uni WL%=;\nWD%=:\n}" \
            :: "r"(_m), "r"(_p) : "memory"); \
    } } while (0)
#define MBAR_ARRIVE_LEADER(a) \
    asm volatile("{\n .reg .b32 la;\n and.b32 la, %0, 0xFEFFFFFF;\n" \
        " mbarrier.arrive.shared::cluster.b64 _, [la];\n}" :: "r"(a) : "memory")
#define CLUSTER_SYNC() do { \
    asm volatile("barrier.cluster.arrive.aligned;" ::: "memory"); \
    asm volatile("barrier.cluster.wait.aligned;" ::: "memory"); } while (0)
#define FENCE_PROXY_ASYNC() asm volatile("fence.proxy.async.shared::cta;" ::: "memory")

__device__ __forceinline__ float fast_ex2(float x) {
    float r; asm("ex2.approx.ftz.f32 %0, %1;" : "=f"(r) : "f"(x)); return r;
}
__device__ __forceinline__ uint32_t pack_bf16x2(float lo, float hi) {
    uint32_t r; asm("cvt.rn.bf16x2.f32 %0, %1, %2;" : "=r"(r) : "f"(hi), "f"(lo)); return r;
}

#define T2M 256
#define T2N 256
#define NST2 3
#define NCHUNK (GK / 64)
#define ST2_BYTES (4 * 16384)
#define GEMM2_SMEM (2048 + NST2 * ST2_BYTES)
#define GEMM2_IDESC ((1u<<4) | (1u<<7) | (1u<<10) | ((T2N/8)<<17) | ((T2M/16)<<24))

// flash: 128-key tiles; K double-buffered, V single-buffered
#define FL_SMEM (2048 + 3 * 65536)
#define TQHI 0
#define TQLO 64
#define TO   128
#define SP(st) (256 + (st) * 128)
#define IDN128 ((1u<<4)|(1u<<7)|(1u<<10)|((128/8)<<17)|((128/16)<<24))
#define B2C  17.0f

#if HAS_TCGEN05

__device__ __forceinline__ uint32_t elect1() {
    uint32_t p;
    asm volatile("{.reg .pred P; elect.sync _|P, 0xFFFFFFFF; selp.b32 %0,1,0,P;}" : "=r"(p));
    return p;
}
#define TCGEN05_ALLOC(a, n) \
    asm volatile("tcgen05.alloc.cta_group::1.sync.aligned.shared::cta.b32 [%0], %1;" :: "r"(a), "r"(n) : "memory")
#define TCGEN05_RELINQ() asm volatile("tcgen05.relinquish_alloc_permit.cta_group::1.sync.aligned;")
#define TCGEN05_DEALLOC(t, n) \
    asm volatile("tcgen05.dealloc.cta_group::1.sync.aligned.b32 %0, %1;" :: "r"(t), "r"(n))
#define TCGEN05_ALLOC_CG2(a, n) \
    asm volatile("tcgen05.alloc.cta_group::2.sync.aligned.shared::cta.b32 [%0], %1;" :: "r"(a), "r"(n) : "memory")
#define TCGEN05_RELINQ_CG2() asm volatile("tcgen05.relinquish_alloc_permit.cta_group::2.sync.aligned;")
#define TCGEN05_DEALLOC_CG2(t, n) \
    asm volatile("tcgen05.dealloc.cta_group::2.sync.aligned.b32 %0, %1;" :: "r"(t), "r"(n))
#define TCGEN05_COMMIT(m) \
    asm volatile("tcgen05.commit.cta_group::1.mbarrier::arrive::one.shared::cluster.b64 [%0];" :: "r"(m) : "memory")
#define TCGEN05_COMMIT_MC_CG2(m, mask) \
    asm volatile("tcgen05.commit.cta_group::2.mbarrier::arrive::one.shared::cluster.multicast::cluster.b64 [%0], %1;" \
        :: "r"(m), "h"((uint16_t)(mask)) : "memory")
#define TCGEN05_FENCE_BEFORE() asm volatile("tcgen05.fence::before_thread_sync;" ::: "memory")
#define TCGEN05_FENCE_AFTER()  asm volatile("tcgen05.fence::after_thread_sync;" ::: "memory")
#define TCGEN05_WAIT_LD() asm volatile("tcgen05.wait::ld.sync.aligned;" ::: "memory")
#define TCGEN05_WAIT_ST() asm volatile("tcgen05.wait::st.sync.aligned;" ::: "memory")

#define LDTM_X32(r, a) \
    asm volatile("tcgen05.ld.sync.aligned.32x32b.x32.b32 " \
        "{%0,%1,%2,%3,%4,%5,%6,%7,%8,%9,%10,%11,%12,%13,%14,%15," \
        "%16,%17,%18,%19,%20,%21,%22,%23,%24,%25,%26,%27,%28,%29,%30,%31}, [%32];" \
        : "=r"((r)[0]),"=r"((r)[1]),"=r"((r)[2]),"=r"((r)[3]),"=r"((r)[4]),"=r"((r)[5]),"=r"((r)[6]),"=r"((r)[7]), \
          "=r"((r)[8]),"=r"((r)[9]),"=r"((r)[10]),"=r"((r)[11]),"=r"((r)[12]),"=r"((r)[13]),"=r"((r)[14]),"=r"((r)[15]), \
          "=r"((r)[16]),"=r"((r)[17]),"=r"((r)[18]),"=r"((r)[19]),"=r"((r)[20]),"=r"((r)[21]),"=r"((r)[22]),"=r"((r)[23]), \
          "=r"((r)[24]),"=r"((r)[25]),"=r"((r)[26]),"=r"((r)[27]),"=r"((r)[28]),"=r"((r)[29]),"=r"((r)[30]),"=r"((r)[31]) \
        : "r"(a))
#define STTM_X32(a, r) \
    asm volatile("tcgen05.st.sync.aligned.32x32b.x32.b32 [%0], " \
        "{%1,%2,%3,%4,%5,%6,%7,%8,%9,%10,%11,%12,%13,%14,%15,%16," \
        "%17,%18,%19,%20,%21,%22,%23,%24,%25,%26,%27,%28,%29,%30,%31,%32};" \
        :: "r"(a), \
           "r"((r)[0]),"r"((r)[1]),"r"((r)[2]),"r"((r)[3]),"r"((r)[4]),"r"((r)[5]),"r"((r)[6]),"r"((r)[7]), \
           "r"((r)[8]),"r"((r)[9]),"r"((r)[10]),"r"((r)[11]),"r"((r)[12]),"r"((r)[13]),"r"((r)[14]),"r"((r)[15]), \
           "r"((r)[16]),"r"((r)[17]),"r"((r)[18]),"r"((r)[19]),"r"((r)[20]),"r"((r)[21]),"r"((r)[22]),"r"((r)[23]), \
           "r"((r)[24]),"r"((r)[25]),"r"((r)[26]),"r"((r)[27]),"r"((r)[28]),"r"((r)[29]),"r"((r)[30]),"r"((r)[31]) \
        : "memory")

__device__ __forceinline__ uint64_t mk_desc(uint32_t addr) {
    const uint64_t base = (uint64_t(2) << 61) | (uint64_t(1) << 46) |
                          (uint64_t(64) << 32) | (uint64_t(1) << 16);
    return base | ((addr >> 4) & 0x3FFF);
}
__device__ __forceinline__ void mma_ss_cg2(uint32_t d, uint64_t ad, uint64_t bd,
                                           uint32_t idesc, uint32_t en) {
    asm volatile("{\n .reg .pred p;\n setp.ne.u32 p, %5, 0;\n"
        " tcgen05.mma.cta_group::2.kind::f16 [%0], %1, %2, %3, "
        "{%4,%4,%4,%4,%4,%4,%4,%4}, p;\n}"
        :: "r"(d), "l"(ad), "l"(bd), "r"(idesc), "r"(0u), "r"(en) : "memory");
}
__device__ __forceinline__ void mma_ts(uint32_t d, uint32_t a, uint64_t bd,
                                       uint32_t idesc, uint32_t en) {
    asm volatile("{\n .reg .pred p;\n setp.ne.u32 p, %4, 0;\n"
        " tcgen05.mma.cta_group::1.kind::f16 [%0], [%1], %2, %3, {%5,%5,%5,%5}, p;\n}"
        :: "r"(d), "r"(a), "l"(bd), "r"(idesc), "r"(en), "r"(0u) : "memory");
}

// ---------------- cg2 bf16x3 GEMM (R13 version, passing) -----------------
__global__ __launch_bounds__(128, 1) __cluster_dims__(2, 1, 1)
void gemm2_kernel(
    float* __restrict__ C,
    const __nv_bfloat16* __restrict__ Ahi, const __nv_bfloat16* __restrict__ Alo,
    const __nv_bfloat16* __restrict__ Bhi, const __nv_bfloat16* __restrict__ Blo,
    int N, int mode, const float* __restrict__ qg)
{
    extern __shared__ char sm[];
    const uint32_t sbase = smem_u32(sm);
    const uint32_t war0  = sbase + 8;
    const uint32_t full0 = sbase + 32;
    const uint32_t tile0 = (sbase + 64 + 1023) & ~1023u;
    const int tid = threadIdx.x, wid = tid >> 5, lid = tid & 31;
    const int rank = blockIdx.x & 1;
    const int bn = (blockIdx.x >> 1) * T2N;
    const int bm = blockIdx.y * T2M;

    if (tid == 0) {
        #pragma unroll
        for (int s = 0; s < NST2; s++) {
            MBAR_INIT(war0 + s * 8, 1);
            MBAR_INIT(full0 + s * 8, 192);
        }
    }
    if (wid == 0) { TCGEN05_ALLOC_CG2(sbase, 256); TCGEN05_RELINQ_CG2(); }
    __syncthreads();
    uint32_t tmem;
    asm volatile("ld.shared.b32 %0, [%1];" : "=r"(tmem) : "r"(sbase));
    CLUSTER_SYNC();

    if (wid >= 1) {
        const int lt = tid - 32;
        const char* Abase = (const char*)Ahi + (size_t)(bm + rank * 128) * (GK * 2);
        const char* Albase = (const char*)Alo + (size_t)(bm + rank * 128) * (GK * 2);
        const char* Bbase = (const char*)Bhi + (size_t)(bn + rank * 128) * (GK * 2);
        const char* Blbase = (const char*)Blo + (size_t)(bn + rank * 128) * (GK * 2);
        auto load_chunk = [&](int c) {
            uint32_t st = tile0 + (c % 3) * ST2_BYTES;
            #pragma unroll
            for (int i = 0; i < 11; i++) {
                int g = lt + i * 96;
                if (g < 1024) {
                    int row = g >> 3, seg = g & 7;
                    uint32_t so = SWZ((uint32_t)(row * 128 + seg * 16));
                    size_t go = (size_t)row * (GK * 2) + c * 128 + seg * 16;
                    CP_ASYNC16(st + so,         Abase + go);
                    CP_ASYNC16(st + 16384 + so, Albase + go);
                    CP_ASYNC16(st + 32768 + so, Bbase + go);
                    CP_ASYNC16(st + 49152 + so, Blbase + go);
                }
            }
        };
        load_chunk(0); CP_COMMIT();
        load_chunk(1); CP_COMMIT();
        for (int c = 0; c < NCHUNK; c++) {
            const int cl = c + 2;
            if (cl < NCHUNK) {
                if (cl >= NST2) MBAR_WAIT(war0 + (cl % 3) * 8, ((cl / 3) + 1) & 1);
                load_chunk(cl);
            }
            CP_COMMIT();
            CP_WAIT(2);
            FENCE_PROXY_ASYNC();
            MBAR_ARRIVE_LEADER(full0 + (c % 3) * 8);
        }
    } else if (rank == 0 && elect1()) {
        for (int c = 0; c < NCHUNK; c++) {
            MBAR_WAIT(full0 + (c % 3) * 8, (c / 3) & 1);
            uint32_t st = tile0 + (c % 3) * ST2_BYTES;
            uint64_t adh = mk_desc(st),         adl = mk_desc(st + 16384);
            uint64_t bdh = mk_desc(st + 32768), bdl = mk_desc(st + 49152);
            #pragma unroll
            for (int s = 0; s < 4; s++)
                mma_ss_cg2(tmem, adh + s * 2, bdh + s * 2, GEMM2_IDESC,
                           (uint32_t)((c | s) != 0));
            #pragma unroll
            for (int s = 0; s < 4; s++)
                mma_ss_cg2(tmem, adl + s * 2, bdh + s * 2, GEMM2_IDESC, 1u);
            #pragma unroll
            for (int s = 0; s < 4; s++)
                mma_ss_cg2(tmem, adh + s * 2, bdl + s * 2, GEMM2_IDESC, 1u);
            TCGEN05_COMMIT_MC_CG2(war0 + (c % 3) * 8, 0x3);
        }
    }

    __syncthreads();
    MBAR_WAIT(war0 + ((NCHUNK - 1) % 3) * 8, ((NCHUNK - 1) / 3) & 1);
    TCGEN05_FENCE_AFTER();

    if (mode == 0) {
        #pragma unroll
        for (int cb = 0; cb < T2N; cb += 32) {
            uint32_t r[32];
            LDTM_X32(r, tmem + cb);
            TCGEN05_WAIT_LD();
            float* Cp = C + (size_t)(bm + rank * 128 + wid * 32 + lid) * N + bn + cb;
            #pragma unroll
            for (int j = 0; j < 8; j++) {
                float4 v;
                v.x = __uint_as_float(r[j*4+0]); v.y = __uint_as_float(r[j*4+1]);
                v.z = __uint_as_float(r[j*4+2]); v.w = __uint_as_float(r[j*4+3]);
                *(float4*)(Cp + j * 4) = v;
            }
        }
    } else {
        char* smc = sm + (tile0 - sbase);
        float* smf = (float*)smc;                    // [128][129]
        float* rng = (float*)(smc + 128 * 129 * 4);
        const int lrow0 = wid * 32 + lid;
        for (int hh = 0; hh < 2; hh++) {
            #pragma unroll
            for (int q = 0; q < 4; q++) {
                uint32_t r[32];
                LDTM_X32(r, tmem + hh * 128 + q * 32);
                TCGEN05_WAIT_LD();
                #pragma unroll
                for (int j = 0; j < 32; j++)
                    smf[lrow0 * 129 + q * 32 + j] = __uint_as_float(r[j]);
            }
            __syncthreads();
            const int head = (bn + hh * 128) >> 7;
            if (head < NHEADS + NKV) {
                const bool isq = head < NHEADS;
                {
                    const float* rp = smf + tid * 129;
                    float ss = 0.f;
                    #pragma unroll 16
                    for (int c = 0; c < 128; c++) { float v = rp[c]; ss = fmaf(v, v, ss); }
                    float rr = rsqrtf(ss * (1.0f / HD) + 1.1920929e-7f);
                    rng[tid] = (isq ? qg[head] * QFAC : 1.0f) * rr;
                }
                __syncthreads();
                __nv_bfloat16* hip = isq ? g_qhi : g_khi;
                __nv_bfloat16* lop = isq ? g_qlo : g_klo;
                for (int rr2 = 0; rr2 < 32; rr2++) {
                    int row = wid * 32 + rr2;
                    int tok = bm + rank * 128 + row;
                    int srow = tok & (SEQ - 1);
                    float g = rng[row];
                    float x0 = smf[row * 129 + lid];
                    float x1 = smf[row * 129 + lid + 32];
                    float x2 = smf[row * 129 + lid + 64];
                    float x3 = smf[row * 129 + lid + 96];
                    float c0 = g_cos[srow * 64 + lid],      s0 = g_sin[srow * 64 + lid];
                    float c1 = g_cos[srow * 64 + lid + 32], s1 = g_sin[srow * 64 + lid + 32];
                    float oa1 = (x0 * c0 + x2 * s0) * g, oa2 = (x2 * c0 - x0 * s0) * g;
                    float ob1 = (x1 * c1 + x3 * s1) * g, ob2 = (x3 * c1 - x1 * s1) * g;
                    size_t ob = isq ? (size_t)tok * DIM + head * HD
                                    : (size_t)tok * KVD + (head - NHEADS) * HD;
                    __nv_bfloat16 ha1 = __float2bfloat16(oa1), ha2 = __float2bfloat16(oa2);
                    __nv_bfloat16 hb1 = __float2bfloat16(ob1), hb2 = __float2bfloat16(ob2);
                    hip[ob + lid]      = ha1;
                    hip[ob + lid + 32] = hb1;
                    hip[ob + lid + 64] = ha2;
                    hip[ob + lid + 96] = hb2;
                    lop[ob + lid]      = __float2bfloat16(oa1 - __bfloat162float(ha1));
                    lop[ob + lid + 32] = __float2bfloat16(ob1 - __bfloat162float(hb1));
                    lop[ob + lid + 64] = __float2bfloat16(oa2 - __bfloat162float(ha2));
                    lop[ob + lid + 96] = __float2bfloat16(ob2 - __bfloat162float(hb2));
                }
            } else {
                for (int rr2 = 0; rr2 < 32; rr2++) {
                    int row = wid * 32 + rr2;
                    int tok = bm + rank * 128 + row;
                    float* vp = C + (size_t)tok * KVD + (head - NHEADS - NKV) * HD;
                    vp[lid]      = smf[row * 129 + lid];
                    vp[lid + 32] = smf[row * 129 + lid + 32];
                    vp[lid + 64] = smf[row * 129 + lid + 64];
                    vp[lid + 96] = smf[row * 129 + lid + 96];
                }
            }
            __syncthreads();
        }
    }
    __syncthreads();
    CLUSTER_SYNC();
    if (wid == 0) TCGEN05_DEALLOC_CG2(tmem, 256);
}

// ---------------- flash: 128-key tiles ------------------------------------
__global__ __launch_bounds__(128, 1) void flash_tc(
    const __nv_bfloat16* __restrict__ Qhi, const __nv_bfloat16* __restrict__ Qlo,
    const __nv_bfloat16* __restrict__ Khi, const __nv_bfloat16* __restrict__ Klo,
    const __nv_bfloat16* __restrict__ Vthi, const __nv_bfloat16* __restrict__ Vtlo,
    __nv_bfloat16* __restrict__ Yhi, __nv_bfloat16* __restrict__ Ylo)
{
    extern __shared__ char sm[];
    const uint32_t sbase  = smem_u32(sm);
    const uint32_t smbar  = sbase;
    const uint32_t pvmbar = sbase + 16;
    const uint32_t tptr   = sbase + 32;
    const uint32_t tile0  = (sbase + 48 + 1023) & ~1023u;

    const int tid = threadIdx.x, wid = tid >> 5;
    const int qtile = gridDim.x - 1 - blockIdx.x;
    const int h = blockIdx.y, b = blockIdx.z, kvh = h >> 2;
    const int q0 = qtile * 128;
    const int nkt = qtile + 1;
    const uint32_t woff = (uint32_t)wid << 21;
    const int row_g = q0 + tid;

    if (tid == 0) {
        MBAR_INIT(smbar, 1);  MBAR_INIT(smbar + 8, 1);
        MBAR_INIT(pvmbar, 1); MBAR_INIT(pvmbar + 8, 1);
    }
    if (wid == 0) { TCGEN05_ALLOC(tptr, 512); TCGEN05_RELINQ(); }
    __syncthreads();
    uint32_t tmem;
    asm volatile("ld.shared.b32 %0, [%1];" : "=r"(tmem) : "r"(tptr));

    // Q rows -> TMEM
    {
        const char* qh = (const char*)Qhi + ((size_t)(b * SEQ + row_g) * DIM + h * HD) * 2;
        const char* ql = (const char*)Qlo + ((size_t)(b * SEQ + row_g) * DIM + h * HD) * 2;
        uint32_t r64[64];
        #pragma unroll
        for (int i = 0; i < 16; i++) {
            uint4 v = *(const uint4*)(qh + i * 16);
            r64[i*4] = v.x; r64[i*4+1] = v.y; r64[i*4+2] = v.z; r64[i*4+3] = v.w;
        }
        STTM_X32(tmem + TQHI + woff, r64);
        STTM_X32(tmem + TQHI + 32 + woff, r64 + 32);
        #pragma unroll
        for (int i = 0; i < 16; i++) {
            uint4 v = *(const uint4*)(ql + i * 16);
            r64[i*4] = v.x; r64[i*4+1] = v.y; r64[i*4+2] = v.z; r64[i*4+3] = v.w;
        }
        STTM_X32(tmem + TQLO + woff, r64);
        STTM_X32(tmem + TQLO + 32 + woff, r64 + 32);
        TCGEN05_WAIT_ST();
    }
    TCGEN05_FENCE_BEFORE();
    __syncthreads();

    const char* khbase = (const char*)Khi + (size_t)kvh * HD * 2;
    const char* klbase = (const char*)Klo + (size_t)kvh * HD * 2;
    const char* vhbase = (const char*)Vthi + ((size_t)(b * NKV + kvh) * HD) * (SEQ * 2);
    const char* vlbase = (const char*)Vtlo + ((size_t)(b * NKV + kvh) * HD) * (SEQ * 2);

    // K tile (128 keys x 256B, blocked atoms): kh(st)=tile0+st*64K, kl=+32K
    auto load_k = [&](int kt) {
        uint32_t kh = tile0 + (kt & 1) * 65536;
        uint32_t kl = kh + 32768;
        int k0 = kt * 128;
        #pragma unroll
        for (int i = 0; i < 16; i++) {
            int g = tid + i * 128;
            int r = g >> 4, c = g & 15;
            uint32_t d = SWZ((uint32_t)(((c >> 3) << 14) + ((r >> 3) << 10) +
                                        ((r & 7) << 7) + ((c & 7) << 4)));
            size_t so = (size_t)(b * SEQ + k0 + r) * (KVD * 2) + c * 16;
            CP_ASYNC16(kh + d, khbase + so);
            CP_ASYNC16(kl + d, klbase + so);
        }
    };
    // V tile (128 dims x 256B): vh=tile0+128K, vl=+32K
    auto load_v = [&](int kt) {
        uint32_t vh = tile0 + 131072;
        uint32_t vl = vh + 32768;
        int k0 = kt * 128;
        #pragma unroll
        for (int i = 0; i < 16; i++) {
            int g = tid + i * 128;
            int r = g >> 4, c = g & 15;
            uint32_t d = SWZ((uint32_t)(((c >> 3) << 14) + ((r >> 3) << 10) +
                                        ((r & 7) << 7) + ((c & 7) << 4)));
            size_t so = (size_t)r * (SEQ * 2) + (size_t)k0 * 2 + c * 16;
            CP_ASYNC16(vh + d, vhbase + so);
            CP_ASYNC16(vl + d, vlbase + so);
        }
    };

    auto issue_qk = [&](int kt) {    // S(st) = Qhi*Khi + Qlo*Khi + Qhi*Klo
        uint32_t kh = tile0 + (kt & 1) * 65536;
        uint64_t dh = mk_desc(kh), dl = mk_desc(kh + 32768);
        uint32_t dst = tmem + SP(kt & 1);
        #pragma unroll
        for (int ks = 0; ks < 8; ks++) {
            uint64_t off = (uint64_t)(((ks >> 2) << 10) + ((ks & 3) << 1));
            mma_ts(dst, tmem + TQHI + ks * 8, dh + off, IDN128, (uint32_t)(ks != 0));
        }
        #pragma unroll
        for (int ks = 0; ks < 8; ks++) {
            uint64_t off = (uint64_t)(((ks >> 2) << 10) + ((ks & 3) << 1));
            mma_ts(dst, tmem + TQLO + ks * 8, dh + off, IDN128, 1u);
        }
        #pragma unroll
        for (int ks = 0; ks < 8; ks++) {
            uint64_t off = (uint64_t)(((ks >> 2) << 10) + ((ks & 3) << 1));
            mma_ts(dst, tmem + TQHI + ks * 8, dl + off, IDN128, 1u);
        }
        TCGEN05_COMMIT(smbar + (kt & 1) * 8);
    };

    auto issue_pv = [&](int kt) {    // O += Phi*Vhi + Plo*Vhi + Phi*Vlo
        uint32_t vh = tile0 + 131072;
        uint64_t dvh = mk_desc(vh), dvl = mk_desc(vh + 32768);
        uint32_t sp = tmem + SP(kt & 1);
        #pragma unroll
        for (int ks = 0; ks < 8; ks++) {
            uint32_t ahi = sp + ((ks < 4) ? ks * 8 : 64 + (ks - 4) * 8);
            uint64_t off = (uint64_t)(((ks >> 2) << 10) + ((ks & 3) << 1));
            mma_ts(tmem + TO, ahi, dvh + off, IDN128, (uint32_t)((kt | ks) != 0));
        }
        #pragma unroll
        for (int ks = 0; ks < 8; ks++) {
            uint32_t alo = sp + 32 + ((ks < 4) ? ks * 8 : 64 + (ks - 4) * 8);
            uint64_t off = (uint64_t)(((ks >> 2) << 10) + ((ks & 3) << 1));
            mma_ts(tmem + TO, alo, dvh + off, IDN128, 1u);
        }
        #pragma unroll
        for (int ks = 0; ks < 8; ks++) {
            uint32_t ahi = sp + ((ks < 4) ? ks * 8 : 64 + (ks - 4) * 8);
            uint64_t off = (uint64_t)(((ks >> 2) << 10) + ((ks & 3) << 1));
            mma_ts(tmem + TO, ahi, dvl + off, IDN128, 1u);
        }
        TCGEN05_COMMIT(pvmbar + (kt & 1) * 8);
    };

    // prologue
    load_k(0); load_v(0); CP_COMMIT();
    if (nkt > 1) load_k(1);
    CP_COMMIT();
    CP_WAIT(1);
    FENCE_PROXY_ASYNC();
    __syncthreads();
    if (wid == 0 && elect1()) { TCGEN05_FENCE_AFTER(); issue_qk(0); }

    float l_reg = 0.f;

    for (int kt = 0; kt < nkt; kt++) {
        const int st = kt & 1;
        if (kt >= 1) {
            MBAR_WAIT(pvmbar + ((kt - 1) & 1) * 8, ((kt - 1) >> 1) & 1);
            load_v(kt);
        }
        CP_COMMIT();
        MBAR_WAIT(smbar + st * 8, (kt >> 1) & 1);
        TCGEN05_FENCE_AFTER();
        if (kt + 2 < nkt) load_k(kt + 2);
        CP_COMMIT();

        // epilogue: keys 64..127 first (S cols 64-127 -> P cols 64-127),
        // then keys 0..63 (S cols 0-63 -> P cols 0-63). In-place WAR via wait_ld.
        const int kb = kt * 128;
        const bool diagt = (kt == nkt - 1) && (qtile == kt);  // last tile == diag
        float l_add = 0.f;
        #pragma unroll
        for (int half = 1; half >= 0; half--) {
            uint32_t sreg[64];
            LDTM_X32(sreg, tmem + SP(st) + half * 64);
            LDTM_X32(sreg + 32, tmem + SP(st) + half * 64 + 32);
            TCGEN05_WAIT_LD();
            uint32_t ph[32], pl[32];
            #pragma unroll
            for (int j2 = 0; j2 < 32; j2++) {
                int key0 = kb + half * 64 + 2 * j2;
                float p0 = fast_ex2(__uint_as_float(sreg[2 * j2])     - B2C);
                float p1 = fast_ex2(__uint_as_float(sreg[2 * j2 + 1]) - B2C);
                if (diagt) {
                    if (key0     > row_g) p0 = 0.f;
                    if (key0 + 1 > row_g) p1 = 0.f;
                }
                l_add += p0 + p1;
                uint32_t h2 = pack_bf16x2(p0, p1);
                ph[j2] = h2;
                pl[j2] = pack_bf16x2(p0 - __uint_as_float(h2 << 16),
                                     p1 - __uint_as_float(h2 & 0xFFFF0000u));
            }
            STTM_X32(tmem + SP(st) + half * 64 + woff, ph);
            STTM_X32(tmem + SP(st) + half * 64 + 32 + woff, pl);
        }
        l_reg += l_add;
        TCGEN05_WAIT_ST();
        TCGEN05_FENCE_BEFORE();
        CP_WAIT(1);            // V(kt) + K(kt+1) resident; K(kt+2) may be in flight
        FENCE_PROXY_ASYNC();
        __syncthreads();

        if (wid == 0 && elect1()) {
            TCGEN05_FENCE_AFTER();
            issue_pv(kt);
            if (kt + 1 < nkt) issue_qk(kt + 1);
        }
    }

    MBAR_WAIT(pvmbar + ((nkt - 1) & 1) * 8, ((nkt - 1) >> 1) & 1);
    TCGEN05_FENCE_AFTER();
    float inv = 1.0f / l_reg;
    char* yh = (char*)Yhi + ((size_t)(b * SEQ + row_g) * DIM + h * HD) * 2;
    char* yl = (char*)Ylo + ((size_t)(b * SEQ + row_g) * DIM + h * HD) * 2;
    #pragma unroll
    for (int blk = 0; blk < 4; blk++) {
        uint32_t o[32];
        LDTM_X32(o, tmem + TO + blk * 32);
        TCGEN05_WAIT_LD();
        uint32_t ph[16], pl[16];
        #pragma unroll
        for (int j = 0; j < 16; j++) {
            float y0 = __uint_as_float(o[2 * j])     * inv;
            float y1 = __uint_as_float(o[2 * j + 1]) * inv;
            uint32_t h2 = pack_bf16x2(y0, y1);
            ph[j] = h2;
            pl[j] = pack_bf16x2(y0 - __uint_as_float(h2 << 16),
                                y1 - __uint_as_float(h2 & 0xFFFF0000u));
        }
        #pragma unroll
        for (int q = 0; q < 4; q++) {
            *(uint4*)(yh + blk * 64 + q * 16) = *(uint4*)&ph[q * 4];
            *(uint4*)(yl + blk * 64 + q * 16) = *(uint4*)&pl[q * 4];
        }
    }
    __syncthreads();
    if (wid == 0) TCGEN05_DEALLOC(tmem, 512);
}

#else  // ---- generic compute_103 fallbacks (valid, never executed) ------

__global__ __launch_bounds__(128, 1) __cluster_dims__(2, 1, 1)
void gemm2_kernel(
    float* __restrict__ C,
    const __nv_bfloat16* __restrict__ Ahi, const __nv_bfloat16* __restrict__ Alo,
    const __nv_bfloat16* __restrict__ Bhi, const __nv_bfloat16* __restrict__ Blo,
    int N, int mode, const float* __restrict__ qg)
{
    const int m = blockIdx.y * T2M + (blockIdx.x & 1) * 128 + threadIdx.x;
    const int n0 = (blockIdx.x >> 1) * T2N;
    float row[T2N];
    for (int n = 0; n < T2N; n++) {
        float s = 0.f;
        for (int k = 0; k < GK; k++) {
            float a = __bfloat162float(Ahi[(size_t)m * GK + k]) +
                      __bfloat162float(Alo[(size_t)m * GK + k]);
            float b = __bfloat162float(Bhi[(size_t)(n0 + n) * GK + k]) +
                      __bfloat162float(Blo[(size_t)(n0 + n) * GK + k]);
            s = fmaf(a, b, s);
        }
        row[n] = s;
    }
    if (mode == 0) {
        for (int n = 0; n < T2N; n++) C[(size_t)m * N + n0 + n] = row[n];
        return;
    }
    const int srow = m & (SEQ - 1);
    for (int hh = 0; hh < 2; hh++) {
        const float* f = row + hh * 128;
        int head = (n0 + hh * 128) >> 7;
        if (head < NHEADS + NKV) {
            float ss = 0.f;
            for (int d = 0; d < 128; d++) ss += f[d] * f[d];
            float rr = rsqrtf(ss * (1.0f / HD) + 1.1920929e-7f);
            bool isq = head < NHEADS;
            float g = (isq ? qg[head] * QFAC : 1.0f) * rr;
            __nv_bfloat16* hip = isq ? g_qhi : g_khi;
            __nv_bfloat16* lop = isq ? g_qlo : g_klo;
            size_t ob = isq ? (size_t)m * DIM + head * HD
                            : (size_t)m * KVD + (head - NHEADS) * HD;
            for (int o = 0; o < 128; o++) {
                int d = o & 63;
                float c = g_cos[srow * 64 + d], sn = g_sin[srow * 64 + d];
                float x1 = f[d], x2 = f[d + 64];
                float v = ((o < 64) ? (x1 * c + x2 * sn) : (x2 * c - x1 * sn)) * g;
                __nv_bfloat16 hv = __float2bfloat16(v);
                hip[ob + o] = hv;
                lop[ob + o] = __float2bfloat16(v - __bfloat162float(hv));
            }
        } else {
            for (int d = 0; d < 128; d++)
                C[(size_t)m * KVD + (head - NHEADS - NKV) * HD + d] = f[d];
        }
    }
}

__global__ __launch_bounds__(128, 1) void flash_tc(
    const __nv_bfloat16* __restrict__ Qhi, const __nv_bfloat16* __restrict__ Qlo,
    const __nv_bfloat16* __restrict__ Khi, const __nv_bfloat16* __restrict__ Klo,
    const __nv_bfloat16* __restrict__ Vthi, const __nv_bfloat16* __restrict__ Vtlo,
    __nv_bfloat16* __restrict__ Yhi, __nv_bfloat16* __restrict__ Ylo)
{
    const int qtile = gridDim.x - 1 - blockIdx.x;
    const int h = blockIdx.y, b = blockIdx.z, kvh = h >> 2;
    const int row = qtile * 128 + threadIdx.x;
    float o[HD], l = 0.f;
    for (int d = 0; d < HD; d++) o[d] = 0.f;
    for (int k = 0; k <= row; k++) {
        float s = 0.f;
        size_t kb = (size_t)(b * SEQ + k) * KVD + kvh * HD;
        size_t qb = (size_t)(b * SEQ + row) * DIM + h * HD;
        for (int d = 0; d < HD; d++)
            s = fmaf(__bfloat162float(Qhi[qb + d]) + __bfloat162float(Qlo[qb + d]),
                     __bfloat162float(Khi[kb + d]) + __bfloat162float(Klo[kb + d]), s);
        float p = exp2f(s - B2C);
        l += p;
        size_t vb = ((size_t)(b * NKV + kvh) * HD) * SEQ + k;
        for (int d = 0; d < HD; d++)
            o[d] += p * (__bfloat162float(Vthi[vb + (size_t)d * SEQ]) +
                         __bfloat162float(Vtlo[vb + (size_t)d * SEQ]));
    }
    float inv = 1.0f / l;
    for (int d = 0; d < HD; d++) {
        float y = o[d] * inv;
        __nv_bfloat16 hh = __float2bfloat16(y);
        size_t idx = (size_t)(b * SEQ + row) * DIM + h * HD + d;
        Yhi[idx] = hh;
        Ylo[idx] = __float2bfloat16(y - __bfloat162float(hh));
    }
}
#endif // HAS_TCGEN05

#define G_X  (NTOK * DIM / 4)
#define G_WQ (DIM * DIM / 4)
#define G_WKV (KVD * DIM / 4)
#define G_TOT (G_X + G_WQ + 2 * G_WKV + G_WQ)
#define ROPE_N (SEQ * 64)

__global__ __launch_bounds__(256) void split_all_kernel(
    const float* __restrict__ x, const float* __restrict__ Wq,
    const float* __restrict__ Wk, const float* __restrict__ Wv,
    const float* __restrict__ Wo)
{
    int i = blockIdx.x * 256 + threadIdx.x;
    if (i >= G_TOT) {
        int idx = i - G_TOT;
        if (idx < ROPE_N) {
            int s = idx >> 6, d = idx & 63;
            double e = (double)(-2.0 * d / (double)HD) * 9.210340371976184;
            float invf = (float)exp(e);
            float fr = (float)s * invf;
            float c, sn;
            sincosf(fr, &sn, &c);
            g_cos[idx] = c;
            g_sin[idx] = sn;
        }
        return;
    }
    const float* src;
    __nv_bfloat16 *hi, *lo;
    int off;
    if (i < G_X) {
        src = x; hi = g_xhi; lo = g_xlo; off = i;
    } else if (i < G_X + G_WQ) {
        src = Wq; hi = g_wqkvhi; lo = g_wqkvlo; off = i - G_X;
    } else if (i < G_X + G_WQ + G_WKV) {
        src = Wk; hi = g_wqkvhi + (size_t)DIM * GK; lo = g_wqkvlo + (size_t)DIM * GK;
        off = i - (G_X + G_WQ);
    } else if (i < G_X + G_WQ + 2 * G_WKV) {
        src = Wv; hi = g_wqkvhi + (size_t)(DIM + KVD) * GK; lo = g_wqkvlo + (size_t)(DIM + KVD) * GK;
        off = i - (G_X + G_WQ + G_WKV);
    } else {
        src = Wo; hi = g_wohi; lo = g_wolo; off = i - (G_X + G_WQ + 2 * G_WKV);
    }
    float4 v = ((const float4*)src)[off];
    __nv_bfloat16 h0 = __float2bfloat16(v.x), h1 = __float2bfloat16(v.y);
    __nv_bfloat16 h2 = __float2bfloat16(v.z), h3 = __float2bfloat16(v.w);
    __nv_bfloat162* H = (__nv_bfloat162*)hi;
    __nv_bfloat162* L = (__nv_bfloat162*)lo;
    H[off*2+0] = __nv_bfloat162(h0, h1);
    H[off*2+1] = __nv_bfloat162(h2, h3);
    L[off*2+0] = __nv_bfloat162(__float2bfloat16(v.x - __bfloat162float(h0)),
                                __float2bfloat16(v.y - __bfloat162float(h1)));
    L[off*2+1] = __nv_bfloat162(__float2bfloat16(v.z - __bfloat162float(h2)),
                                __float2bfloat16(v.w - __bfloat162float(h3)));
}

__global__ __launch_bounds__(256) void vtrans_split_kernel(
    const float* __restrict__ V, int rowstride)
{
    __shared__ float t[32][33];
    const int ti = blockIdx.x, di = blockIdx.y, bk = blockIdx.z;
    const int b = bk >> 2, kvh = bk & 3;
    const int tx = threadIdx.x & 31, ty = threadIdx.x >> 5;
    #pragma unroll
    for (int i = 0; i < 4; i++) {
        int tok = ti * 32 + ty + i * 8;
        t[ty + i * 8][tx] = V[(size_t)(b * SEQ + tok) * rowstride + kvh * HD + di * 32 + tx];
    }
    __syncthreads();
    #pragma unroll
    for (int i = 0; i < 4; i++) {
        int d = di * 32 + ty + i * 8;
        float v = t[tx][ty + i * 8];
        __nv_bfloat16 hh = __float2bfloat16(v);
        size_t o = ((size_t)(bk * HD + d)) * SEQ + ti * 32 + tx;
        g_vthi[o] = hh;
        g_vtlo[o] = __float2bfloat16(v - __bfloat162float(hh));
    }
}

extern "C" void kernel_launch(void* const* d_in, const int* in_sizes, int n_in,
                              void* d_out, int out_size)
{
    const float* x  = (const float*)d_in[0];
    const float* Wq = (const float*)d_in[1];
    const float* Wk = (const float*)d_in[2];
    const float* Wv = (const float*)d_in[3];
    const float* Wo = (const float*)d_in[4];
    const float* qg = (const float*)d_in[5];
    float* out = (float*)d_out;

    float *vbuf;
    __nv_bfloat16 *xhi, *xlo, *yhi, *ylo, *qhi, *qlo, *khi, *klo;
    __nv_bfloat16 *wqkvh, *wqkvl, *woh, *wol, *vthi, *vtlo;
    cudaGetSymbolAddress((void**)&vbuf, g_qkv);
    cudaGetSymbolAddress((void**)&xhi, g_xhi);
    cudaGetSymbolAddress((void**)&xlo, g_xlo);
    cudaGetSymbolAddress((void**)&yhi, g_yhi);
    cudaGetSymbolAddress((void**)&ylo, g_ylo);
    cudaGetSymbolAddress((void**)&qhi, g_qhi);
    cudaGetSymbolAddress((void**)&qlo, g_qlo);
    cudaGetSymbolAddress((void**)&khi, g_khi);
    cudaGetSymbolAddress((void**)&klo, g_klo);
    cudaGetSymbolAddress((void**)&vthi, g_vthi);
    cudaGetSymbolAddress((void**)&vtlo, g_vtlo);
    cudaGetSymbolAddress((void**)&wqkvh, g_wqkvhi);
    cudaGetSymbolAddress((void**)&wqkvl, g_wqkvlo);
    cudaGetSymbolAddress((void**)&woh, g_wohi);
    cudaGetSymbolAddress((void**)&wol, g_wolo);

    cudaFuncSetAttribute(gemm2_kernel,
                         cudaFuncAttributeMaxDynamicSharedMemorySize, GEMM2_SMEM);
    cudaFuncSetAttribute(flash_tc,
                         cudaFuncAttributeMaxDynamicSharedMemorySize, FL_SMEM);

    split_all_kernel<<<(G_TOT + ROPE_N + 255) / 256, 256>>>(x, Wq, Wk, Wv, Wo);

    gemm2_kernel<<<dim3((QKVD / T2N) * 2, NTOK / T2M), 128, GEMM2_SMEM>>>(
        vbuf, xhi, xlo, wqkvh, wqkvl, QKVD, 1, qg);

    vtrans_split_kernel<<<dim3(SEQ / 32, HD / 32, BSZ * NKV), 256>>>(vbuf, KVD);

    flash_tc<<<dim3(SEQ / 128, NHEADS, BSZ), 128, FL_SMEM>>>(
        qhi, qlo, khi, klo, vthi, vtlo, yhi, ylo);

    gemm2_kernel<<<dim3((DIM / T2N) * 2, NTOK / T2M), 128, GEMM2_SMEM>>>(
        out, yhi, ylo, woh, wol, DIM, 0, qg);
}